// round 7
// baseline (speedup 1.0000x reference)
#include <cuda_runtime.h>
#include <cuda_bf16.h>
#include <cstdint>

#define B_   4
#define L1_  1024
#define D_   256
#define H_   8
#define HD_  32
#define L_   4
#define L2_  21760
#define NQ_  (B_ * L1_)          // 4096
#define MV_  (B_ * L2_)          // 87040

// ---------------- scratch (static device memory; no allocs) ----------------
__device__ float g_v[(size_t)MV_ * D_];        // value @ Wv^T  (89 MB)
__device__ float g_off[(size_t)NQ_ * 128];     // query @ Wbox^T + bbox
__device__ float g_aw[(size_t)NQ_ * 128];      // raw query @ Wattn^T + battn
__device__ float g_outpre[(size_t)NQ_ * D_];   // pre-projection out
__device__ float g_moutpre[(size_t)NQ_ * D_];  // pre-projection mout

// ===========================================================================
// HMMA (mma.sync) helpers — valid on plain sm_103 target.
// ===========================================================================
__device__ __forceinline__ uint32_t smem_u32(const void* p) {
    uint32_t a;
    asm("{ .reg .u64 t; cvta.to.shared.u64 t, %1; cvt.u32.u64 %0, t; }"
        : "=r"(a) : "l"(p));
    return a;
}
__device__ __forceinline__ void ldmx4(uint32_t addr, uint32_t& r0, uint32_t& r1,
                                      uint32_t& r2, uint32_t& r3) {
    asm volatile("ldmatrix.sync.aligned.m8n8.x4.shared.b16 {%0,%1,%2,%3}, [%4];"
                 : "=r"(r0), "=r"(r1), "=r"(r2), "=r"(r3) : "r"(addr));
}
__device__ __forceinline__ void mma16816(float* d, const uint32_t* a,
                                         const uint32_t* b) {
    asm volatile("mma.sync.aligned.m16n8k16.row.col.f32.bf16.bf16.f32 "
                 "{%0,%1,%2,%3}, {%4,%5,%6,%7}, {%8,%9}, {%0,%1,%2,%3};"
                 : "+f"(d[0]), "+f"(d[1]), "+f"(d[2]), "+f"(d[3])
                 : "r"(a[0]), "r"(a[1]), "r"(a[2]), "r"(a[3]),
                   "r"(b[0]), "r"(b[1]));
}

// ===========================================================================
// HMMA GEMM: C[M,256] = A[M,256] @ W[256,256]^T + bias, optional row mask.
// bf16 hi/lo split (3 passes) with fp32 acc. CTA tile 128x256, 512 threads
// (16 warps = 4 M-blocks x 4 N-blocks, warp tile 32x64), BK=16.
// A loaded + converted exactly once.
// ===========================================================================
#define RS_ 48   // smem row stride bytes for 16 bf16 (32B data + 16B pad)

__global__ __launch_bounds__(512)
void hmma_gemm256(const float* __restrict__ A,
                  const float* __restrict__ W,
                  const float* __restrict__ bias,
                  float* __restrict__ C,
                  const unsigned char* __restrict__ mask)
{
    __shared__ __align__(16) unsigned char smAh[128 * RS_];
    __shared__ __align__(16) unsigned char smAl[128 * RS_];
    __shared__ __align__(16) unsigned char smBh[256 * RS_];
    __shared__ __align__(16) unsigned char smBl[256 * RS_];
    __shared__ float bias_s[256];

    const int t    = threadIdx.x;
    const int wid  = t >> 5;
    const int lane = t & 31;
    const int wm   = wid & 3;       // M block (32 rows)
    const int wn   = wid >> 2;      // N block (64 cols)
    const int m0   = blockIdx.x * 128;

    if (t < 256) bias_s[t] = bias[t];

    float acc[2][8][4];
#pragma unroll
    for (int mt = 0; mt < 2; mt++)
#pragma unroll
        for (int nt = 0; nt < 8; nt++)
#pragma unroll
            for (int i = 0; i < 4; i++) acc[mt][nt][i] = 0.f;

    const uint32_t uAh = smem_u32(smAh);
    const uint32_t uAl = smem_u32(smAl);
    const uint32_t uBh = smem_u32(smBh);
    const uint32_t uBl = smem_u32(smBl);

    for (int k0 = 0; k0 < 256; k0 += 16) {
        // ---- stage A(128x16) fp32 -> bf16 hi/lo ----
        {
            int r  = t >> 2;          // 0..127
            int c4 = t & 3;
            float4 v = *(const float4*)(A + (size_t)(m0 + r) * 256 + k0 + c4 * 4);
            __nv_bfloat162 h01 = __floats2bfloat162_rn(v.x, v.y);
            __nv_bfloat162 h23 = __floats2bfloat162_rn(v.z, v.w);
            float2 f01 = __bfloat1622float2(h01);
            float2 f23 = __bfloat1622float2(h23);
            __nv_bfloat162 l01 = __floats2bfloat162_rn(v.x - f01.x, v.y - f01.y);
            __nv_bfloat162 l23 = __floats2bfloat162_rn(v.z - f23.x, v.w - f23.y);
            *(__nv_bfloat162*)(smAh + r * RS_ + c4 * 8)     = h01;
            *(__nv_bfloat162*)(smAh + r * RS_ + c4 * 8 + 4) = h23;
            *(__nv_bfloat162*)(smAl + r * RS_ + c4 * 8)     = l01;
            *(__nv_bfloat162*)(smAl + r * RS_ + c4 * 8 + 4) = l23;
        }
        // ---- stage W(256x16) fp32 -> bf16 hi/lo ----
#pragma unroll
        for (int u = 0; u < 2; u++) {
            int f  = t + u * 512;
            int r  = f >> 2;          // 0..255
            int c4 = f & 3;
            float4 w = *(const float4*)(W + (size_t)r * 256 + k0 + c4 * 4);
            __nv_bfloat162 h01 = __floats2bfloat162_rn(w.x, w.y);
            __nv_bfloat162 h23 = __floats2bfloat162_rn(w.z, w.w);
            float2 f01 = __bfloat1622float2(h01);
            float2 f23 = __bfloat1622float2(h23);
            __nv_bfloat162 l01 = __floats2bfloat162_rn(w.x - f01.x, w.y - f01.y);
            __nv_bfloat162 l23 = __floats2bfloat162_rn(w.z - f23.x, w.w - f23.y);
            *(__nv_bfloat162*)(smBh + r * RS_ + c4 * 8)     = h01;
            *(__nv_bfloat162*)(smBh + r * RS_ + c4 * 8 + 4) = h23;
            *(__nv_bfloat162*)(smBl + r * RS_ + c4 * 8)     = l01;
            *(__nv_bfloat162*)(smBl + r * RS_ + c4 * 8 + 4) = l23;
        }
        __syncthreads();

        // ---- one k16 step ----
        uint32_t ah[2][4], al[2][4];
#pragma unroll
        for (int mt = 0; mt < 2; mt++) {
            int row  = wm * 32 + mt * 16 + (lane & 15);
            int koff = (lane >> 4) << 4;
            ldmx4(uAh + row * RS_ + koff, ah[mt][0], ah[mt][1], ah[mt][2], ah[mt][3]);
            ldmx4(uAl + row * RS_ + koff, al[mt][0], al[mt][1], al[mt][2], al[mt][3]);
        }
#pragma unroll
        for (int half = 0; half < 2; half++) {
            uint32_t bh[4][2], bl[4][2];
#pragma unroll
            for (int p = 0; p < 2; p++) {
                int pp   = half * 2 + p;
                int nrow = wn * 64 + pp * 16 + (lane & 7) + (((lane >> 4) & 1) << 3);
                int koff = ((lane >> 3) & 1) << 4;
                ldmx4(uBh + nrow * RS_ + koff,
                      bh[p*2][0], bh[p*2][1], bh[p*2+1][0], bh[p*2+1][1]);
                ldmx4(uBl + nrow * RS_ + koff,
                      bl[p*2][0], bl[p*2][1], bl[p*2+1][0], bl[p*2+1][1]);
            }
#pragma unroll
            for (int mt = 0; mt < 2; mt++)
#pragma unroll
                for (int q = 0; q < 4; q++) {
                    int nt = half * 4 + q;
                    mma16816(acc[mt][nt], ah[mt], bh[q]);
                    mma16816(acc[mt][nt], ah[mt], bl[q]);
                    mma16816(acc[mt][nt], al[mt], bh[q]);
                }
        }
        __syncthreads();
    }

    // ---- epilogue: bias + mask, direct float2 stores ----
    const int rw = lane >> 2;
    const int cw = (lane & 3) * 2;
#pragma unroll
    for (int mt = 0; mt < 2; mt++) {
        int r = m0 + wm * 32 + mt * 16 + rw;
        bool z0 = (mask != nullptr) && (mask[r] != 0);
        bool z1 = (mask != nullptr) && (mask[r + 8] != 0);
#pragma unroll
        for (int nt = 0; nt < 8; nt++) {
            int cl = wn * 64 + nt * 8 + cw;
            float b0 = bias_s[cl], b1 = bias_s[cl + 1];
            float2 v0, v1;
            v0.x = z0 ? 0.f : acc[mt][nt][0] + b0;
            v0.y = z0 ? 0.f : acc[mt][nt][1] + b1;
            v1.x = z1 ? 0.f : acc[mt][nt][2] + b0;
            v1.y = z1 ? 0.f : acc[mt][nt][3] + b1;
            *(float2*)(C + (size_t)r * 256 + cl)       = v0;
            *(float2*)(C + (size_t)(r + 8) * 256 + cl) = v1;
        }
    }
}

// ---------------------------------------------------------------------------
// SIMT GEMM for the small N=128 projections (off / aw).
// ---------------------------------------------------------------------------
#define SA_ 68
__global__ void gemm_bias_kernel(const float* __restrict__ A,
                                 const float* __restrict__ W,
                                 const float* __restrict__ bias,
                                 float* __restrict__ C,
                                 int M, int N, int K)
{
    __shared__ float As[32 * SA_];
    __shared__ float Bs[32 * SA_];

    const int m0 = blockIdx.x * 64;
    const int n0 = blockIdx.y * 64;
    const int t  = threadIdx.x;
    const int tm = t >> 4;
    const int tn = t & 15;

    float acc[4][4];
#pragma unroll
    for (int i = 0; i < 4; i++)
#pragma unroll
        for (int j = 0; j < 4; j++) acc[i][j] = 0.f;

    for (int k0 = 0; k0 < K; k0 += 32) {
#pragma unroll
        for (int u = 0; u < 2; u++) {
            int f   = t + u * 256;
            int row = f >> 3;
            int kc  = (f & 7) << 2;
            float4 a4 = *(const float4*)(A + (size_t)(m0 + row) * K + k0 + kc);
            As[(kc + 0) * SA_ + row] = a4.x;
            As[(kc + 1) * SA_ + row] = a4.y;
            As[(kc + 2) * SA_ + row] = a4.z;
            As[(kc + 3) * SA_ + row] = a4.w;
            float4 b4 = *(const float4*)(W + (size_t)(n0 + row) * K + k0 + kc);
            Bs[(kc + 0) * SA_ + row] = b4.x;
            Bs[(kc + 1) * SA_ + row] = b4.y;
            Bs[(kc + 2) * SA_ + row] = b4.z;
            Bs[(kc + 3) * SA_ + row] = b4.w;
        }
        __syncthreads();

#pragma unroll
        for (int k = 0; k < 32; k++) {
            float4 av = *(const float4*)(As + k * SA_ + tm * 4);
            float4 bv = *(const float4*)(Bs + k * SA_ + tn * 4);
            float ar[4] = {av.x, av.y, av.z, av.w};
            float br[4] = {bv.x, bv.y, bv.z, bv.w};
#pragma unroll
            for (int i = 0; i < 4; i++)
#pragma unroll
                for (int j = 0; j < 4; j++) acc[i][j] += ar[i] * br[j];
        }
        __syncthreads();
    }

#pragma unroll
    for (int i = 0; i < 4; i++) {
        int r = m0 + tm * 4 + i;
        int c = n0 + tn * 4;
        float4 o;
        o.x = acc[i][0] + bias[c + 0];
        o.y = acc[i][1] + bias[c + 1];
        o.z = acc[i][2] + bias[c + 2];
        o.w = acc[i][3] + bias[c + 3];
        *(float4*)(C + (size_t)r * N + c) = o;
    }
}

// ---------------------------------------------------------------------------
// Sampler v2: 1 block per query, 256 threads.
// Phase 1: 512 thread-slots compute per-sample gather indices + bilinear
//          weights ONCE (no 32x duplication). Phase 2: warp = head gathers.
// ---------------------------------------------------------------------------
__global__ __launch_bounds__(256)
void sample_kernel(const float* __restrict__ refwin,
                   float* __restrict__ awout)
{
    __shared__ float  sh_raw[128];
    __shared__ float  sh_off[128];
    __shared__ float2 sh_swlw[H_][64];
    __shared__ int4   sh_idx[512];
    __shared__ float4 sh_w[512];

    const int bq   = blockIdx.x;
    const int b    = bq >> 10;
    const int t    = threadIdx.x;
    const int h    = t >> 5;
    const int lane = t & 31;

    if (t < 128) sh_raw[t] = g_aw[(size_t)bq * 128 + t];
    else         sh_off[t - 128] = g_off[(size_t)bq * 128 + (t - 128)];
    __syncthreads();

    // ---- softmaxes (warp = head), same math as passing R6 kernel ----
    float e[2];
    int   aidx[2];
#pragma unroll
    for (int tgt = 0; tgt < 2; tgt++) {
        int n = lane + 32 * tgt;
        int l = n >> 4, kk = n & 15, ii = kk >> 2, jj = kk & 3;
        int a = ((ii >> 1) << 1) + (jj >> 1);
        aidx[tgt] = a;
        e[tgt] = sh_raw[h * 16 + l * 4 + a];
    }
    awout[(size_t)bq * 512 + h * 64 + lane]      = e[0];
    awout[(size_t)bq * 512 + h * 64 + lane + 32] = e[1];

    float m = fmaxf(e[0], e[1]);
#pragma unroll
    for (int o = 16; o > 0; o >>= 1) m = fmaxf(m, __shfl_xor_sync(0xffffffffu, m, o));
    float p0 = __expf(e[0] - m), p1 = __expf(e[1] - m);
    float s = p0 + p1;
#pragma unroll
    for (int o = 16; o > 0; o >>= 1) s += __shfl_xor_sync(0xffffffffu, s, o);
    float inv = 1.f / s;

#pragma unroll
    for (int tgt = 0; tgt < 2; tgt++) {
        int a = aidx[tgt];
        float r0 = sh_raw[h * 16 + 0 + a], r1 = sh_raw[h * 16 + 4 + a];
        float r2 = sh_raw[h * 16 + 8 + a], r3 = sh_raw[h * 16 + 12 + a];
        float m4 = fmaxf(fmaxf(r0, r1), fmaxf(r2, r3));
        float s4 = __expf(r0 - m4) + __expf(r1 - m4) + __expf(r2 - m4) + __expf(r3 - m4);
        float lw = __expf(e[tgt] - m4) / s4;
        float sw = (tgt == 0 ? p0 : p1) * inv;
        sh_swlw[h][lane + 32 * tgt] = make_float2(sw, lw);
    }

    // ---- phase 1: per-sample indices + weights (computed once) ----
    const float rcx = refwin[bq * 4 + 0];
    const float rcy = refwin[bq * 4 + 1];
    const float rsx = refwin[bq * 4 + 2];
    const float rsy = refwin[bq * 4 + 3];

#pragma unroll
    for (int rep = 0; rep < 2; rep++) {
        int sidx = t + rep * 256;         // 0..511 = hh*64 + n
        int hh = sidx >> 6;
        int n  = sidx & 63;
        int l  = n >> 4;
        int ii = (n >> 2) & 3;
        int jj = n & 3;

        float o0 = sh_off[hh * 16 + l * 4 + 0];
        float o1 = sh_off[hh * 16 + l * 4 + 1];
        float o2 = sh_off[hh * 16 + l * 4 + 2];
        float o3 = sh_off[hh * 16 + l * 4 + 3];
        float cx = rcx + o0 * 0.125f * rsx;
        float cy = rcy + o1 * 0.125f * rsy;
        float sx = fmaxf(rsx + o2 * 0.125f * rsx, 0.f);
        float sy = fmaxf(rsy + o3 * 0.125f * rsy, 0.f);

        int   Wl  = 128 >> l;
        float fW  = (float)Wl;
        int base  = (l == 0) ? 0 : (l == 1) ? 16384 : (l == 2) ? 20480 : 21504;

        float y   = (cy + ((float)ii - 1.5f) * 0.25f * sy) * fW - 0.5f;
        float x   = (cx + ((float)jj - 1.5f) * 0.25f * sx) * fW - 0.5f;
        float y0f = floorf(y);
        float x0f = floorf(x);
        float fy  = y - y0f;
        float fx  = x - x0f;
        int y0 = (int)y0f;
        int x0 = (int)x0f;
        bool vy0 = (y0 >= 0) && (y0 < Wl);
        bool vy1 = (y0 >= -1) && (y0 < Wl - 1);
        bool vx0 = (x0 >= 0) && (x0 < Wl);
        bool vx1 = (x0 >= -1) && (x0 < Wl - 1);
        int cy0 = min(max(y0, 0), Wl - 1);
        int cy1 = min(max(y0 + 1, 0), Wl - 1);
        int cx0 = min(max(x0, 0), Wl - 1);
        int cx1 = min(max(x0 + 1, 0), Wl - 1);

        int4 id;
        id.x = (base + cy0 * Wl + cx0) * 256;
        id.y = (base + cy0 * Wl + cx1) * 256;
        id.z = (base + cy1 * Wl + cx0) * 256;
        id.w = (base + cy1 * Wl + cx1) * 256;
        float4 w;
        w.x = (vx0 && vy0) ? (1.f - fx) * (1.f - fy) : 0.f;
        w.y = (vx1 && vy0) ? fx * (1.f - fy) : 0.f;
        w.z = (vx0 && vy1) ? (1.f - fx) * fy : 0.f;
        w.w = (vx1 && vy1) ? fx * fy : 0.f;
        sh_idx[sidx] = id;
        sh_w[sidx]   = w;
    }
    __syncthreads();

    // ---- phase 2: gather + weighted accumulation (warp = head) ----
    const float* vb = g_v + (size_t)b * L2_ * 256 + h * 32 + lane;
    float acc_o = 0.f, acc_m = 0.f;

#pragma unroll 8
    for (int n = 0; n < 64; n++) {
        int4   id = sh_idx[h * 64 + n];
        float4 w  = sh_w[h * 64 + n];
        float val = w.x * vb[id.x] + w.y * vb[id.y]
                  + w.z * vb[id.z] + w.w * vb[id.w];
        float2 sl = sh_swlw[h][n];
        acc_o += sl.x * val;
        acc_m += sl.y * val;
    }

    const size_t od = (size_t)bq * D_ + h * HD_ + lane;
    g_outpre[od]  = acc_o;
    g_moutpre[od] = acc_m;
}

// ---------------------------------------------------------------------------
extern "C" void kernel_launch(void* const* d_in, const int* in_sizes, int n_in,
                              void* d_out, int out_size)
{
    const float* query = (const float*)d_in[0];
    const float* value = (const float*)d_in[1];
    const float* refw  = (const float*)d_in[2];
    const float* Wv    = (const float*)d_in[3];
    const float* bv    = (const float*)d_in[4];
    const float* Wo    = (const float*)d_in[5];
    const float* bo    = (const float*)d_in[6];
    const float* Wbox  = (const float*)d_in[7];
    const float* bbox  = (const float*)d_in[8];
    const float* Wattn = (const float*)d_in[9];
    const float* battn = (const float*)d_in[10];
    const unsigned char* vmask = (const unsigned char*)d_in[13];

    float* out   = (float*)d_out;
    float* mout  = out  + (size_t)NQ_ * D_;
    float* awout = mout + (size_t)NQ_ * D_;

    float *pv, *poff, *paw, *pop, *pmp;
    cudaGetSymbolAddress((void**)&pv,   g_v);
    cudaGetSymbolAddress((void**)&poff, g_off);
    cudaGetSymbolAddress((void**)&paw,  g_aw);
    cudaGetSymbolAddress((void**)&pop,  g_outpre);
    cudaGetSymbolAddress((void**)&pmp,  g_moutpre);

    // 1) v = value @ Wv^T + bv, masked   (HMMA, A single-pass)
    hmma_gemm256<<<MV_ / 128, 512>>>(value, Wv, bv, pv, vmask);
    // 2) off = query @ Wbox^T + bbox
    gemm_bias_kernel<<<dim3(NQ_ / 64, 2), 256>>>(query, Wbox, bbox, poff,
                                                 NQ_, 128, D_);
    // 3) raw aw = query @ Wattn^T + battn
    gemm_bias_kernel<<<dim3(NQ_ / 64, 2), 256>>>(query, Wattn, battn, paw,
                                                 NQ_, 128, D_);
    // 4) softmaxes + sampling
    sample_kernel<<<NQ_, 256>>>(refw, awout);
    // 5) out / mout projections          (HMMA)
    hmma_gemm256<<<NQ_ / 128, 512>>>(pop, Wo, bo, out, nullptr);
    hmma_gemm256<<<NQ_ / 128, 512>>>(pmp, Wo, bo, mout, nullptr);
}

// round 9
// speedup vs baseline: 1.1967x; 1.1967x over previous
#include <cuda_runtime.h>
#include <cuda_fp16.h>
#include <cstdint>
#include <cstring>

#define B_   4
#define L1_  1024
#define D_   256
#define H_   8
#define HD_  32
#define L_   4
#define L2_  21760
#define NQ_  (B_ * L1_)          // 4096
#define MV_  (B_ * L2_)          // 87040

// ---------------- scratch (static device memory; no allocs) ----------------
__device__ float  g_v[(size_t)MV_ * D_];        // value @ Wv^T  (89 MB)
__device__ float  g_off[(size_t)NQ_ * 128];
__device__ float  g_aw[(size_t)NQ_ * 128];
__device__ float  g_outpre[(size_t)NQ_ * D_];
__device__ float  g_moutpre[(size_t)NQ_ * D_];
__device__ __half g_Wvh[65536], g_Wvl[65536];   // Wv fp16 hi/lo
__device__ __half g_Woh[65536], g_Wol[65536];   // Wo fp16 hi/lo

// ===========================================================================
// helpers
// ===========================================================================
__device__ __forceinline__ uint32_t h2_bits(__half2 h) {
    uint32_t u;
    memcpy(&u, &h, 4);
    return u;
}
__device__ __forceinline__ uint32_t smem_u32(const void* p) {
    uint32_t a;
    asm("{ .reg .u64 t; cvta.to.shared.u64 t, %1; cvt.u32.u64 %0, t; }"
        : "=r"(a) : "l"(p));
    return a;
}
__device__ __forceinline__ void ldmx4(uint32_t addr, uint32_t& r0, uint32_t& r1,
                                      uint32_t& r2, uint32_t& r3) {
    asm volatile("ldmatrix.sync.aligned.m8n8.x4.shared.b16 {%0,%1,%2,%3}, [%4];"
                 : "=r"(r0), "=r"(r1), "=r"(r2), "=r"(r3) : "r"(addr));
}
__device__ __forceinline__ void mma16816(float* d, const uint32_t* a,
                                         const uint32_t* b) {
    asm volatile("mma.sync.aligned.m16n8k16.row.col.f32.f16.f16.f32 "
                 "{%0,%1,%2,%3}, {%4,%5,%6,%7}, {%8,%9}, {%0,%1,%2,%3};"
                 : "+f"(d[0]), "+f"(d[1]), "+f"(d[2]), "+f"(d[3])
                 : "r"(a[0]), "r"(a[1]), "r"(a[2]), "r"(a[3]),
                   "r"(b[0]), "r"(b[1]));
}

// ---------------------------------------------------------------------------
// prep: Wv / Wo fp32 -> fp16 hi/lo (runs once per launch, ~2us)
// ---------------------------------------------------------------------------
__global__ void prep_w_kernel(const float* __restrict__ Wv,
                              const float* __restrict__ Wo)
{
    int i = blockIdx.x * blockDim.x + threadIdx.x;   // 0..65535
    float v = Wv[i];
    __half h = __float2half_rn(v);
    g_Wvh[i] = h;
    g_Wvl[i] = __float2half_rn(v - __half2float(h));
    float o = Wo[i];
    __half ho = __float2half_rn(o);
    g_Woh[i] = ho;
    g_Wol[i] = __float2half_rn(o - __half2float(ho));
}

// ===========================================================================
// HMMA GEMM: C[M,256] = A[M,256] @ W[256,256]^T + bias, optional row mask.
// A rounded to fp16 in-kernel; W pre-split fp16 hi/lo (2 MMA passes).
// CTA tile 128x256, 512 threads (16 warps = 4Mx4N, warp tile 32x64), BK=32.
// Smem rows are 64B (32 fp16) with XOR swizzle of the 16B unit.
// ===========================================================================
__global__ __launch_bounds__(512)
void hmma_gemm_fp16(const float* __restrict__ A,
                    const __half* __restrict__ Wh,
                    const __half* __restrict__ Wl,
                    const float* __restrict__ bias,
                    float* __restrict__ C,
                    const unsigned char* __restrict__ mask)
{
    __shared__ __align__(16) unsigned char smA [128 * 64];
    __shared__ __align__(16) unsigned char smBh[256 * 64];
    __shared__ __align__(16) unsigned char smBl[256 * 64];
    __shared__ float bias_s[256];

    const int t    = threadIdx.x;
    const int wid  = t >> 5;
    const int lane = t & 31;
    const int wm   = wid & 3;       // M block (32 rows)
    const int wn   = wid >> 2;      // N block (64 cols)
    const int m0   = blockIdx.x * 128;

    if (t < 256) bias_s[t] = bias[t];

    float acc[2][8][4];
#pragma unroll
    for (int mt = 0; mt < 2; mt++)
#pragma unroll
        for (int nt = 0; nt < 8; nt++)
#pragma unroll
            for (int i = 0; i < 4; i++) acc[mt][nt][i] = 0.f;

    const uint32_t uA  = smem_u32(smA);
    const uint32_t uBh = smem_u32(smBh);
    const uint32_t uBl = smem_u32(smBl);

    for (int k0 = 0; k0 < 256; k0 += 32) {
        // ---- stage A(128x32) fp32 -> fp16 (one 16B unit per thread) ----
        {
            int r  = t >> 2;          // 0..127
            int c4 = t & 3;           // 16B unit (8 fp16 = 8 cols)
            const float* src = A + (size_t)(m0 + r) * 256 + k0 + c4 * 8;
            float4 v0 = *(const float4*)(src);
            float4 v1 = *(const float4*)(src + 4);
            uint4 u;
            u.x = h2_bits(__floats2half2_rn(v0.x, v0.y));
            u.y = h2_bits(__floats2half2_rn(v0.z, v0.w));
            u.z = h2_bits(__floats2half2_rn(v1.x, v1.y));
            u.w = h2_bits(__floats2half2_rn(v1.z, v1.w));
            *(uint4*)(smA + r * 64 + (c4 ^ ((r >> 1) & 3)) * 16) = u;
        }
        // ---- stage W hi/lo (256x32 fp16 each): plain 16B copies ----
#pragma unroll
        for (int u = 0; u < 2; u++) {
            int f   = t + u * 512;    // 0..1023
            int r   = f >> 2;         // 0..255
            int c16 = f & 3;
            uint32_t dst = r * 64 + (c16 ^ ((r >> 1) & 3)) * 16;
            *(uint4*)(smBh + dst) = *(const uint4*)(Wh + (size_t)r * 256 + k0 + c16 * 8);
            *(uint4*)(smBl + dst) = *(const uint4*)(Wl + (size_t)r * 256 + k0 + c16 * 8);
        }
        __syncthreads();

#pragma unroll
        for (int s = 0; s < 2; s++) {              // two k16 steps
            uint32_t ah[2][4];
#pragma unroll
            for (int mt = 0; mt < 2; mt++) {
                int row  = wm * 32 + mt * 16 + (lane & 15);
                int unit = s * 2 + (lane >> 4);
                ldmx4(uA + row * 64 + (unit ^ ((row >> 1) & 3)) * 16,
                      ah[mt][0], ah[mt][1], ah[mt][2], ah[mt][3]);
            }
#pragma unroll
            for (int half = 0; half < 2; half++) {
                uint32_t bh[4][2], bl[4][2];
#pragma unroll
                for (int p = 0; p < 2; p++) {
                    int pp   = half * 2 + p;
                    int nrow = wn * 64 + pp * 16 + (lane & 7) + (((lane >> 4) & 1) << 3);
                    int unit = s * 2 + ((lane >> 3) & 1);
                    uint32_t off = nrow * 64 + (unit ^ ((nrow >> 1) & 3)) * 16;
                    ldmx4(uBh + off, bh[p*2][0], bh[p*2][1], bh[p*2+1][0], bh[p*2+1][1]);
                    ldmx4(uBl + off, bl[p*2][0], bl[p*2][1], bl[p*2+1][0], bl[p*2+1][1]);
                }
#pragma unroll
                for (int mt = 0; mt < 2; mt++)
#pragma unroll
                    for (int q = 0; q < 4; q++) {
                        int nt = half * 4 + q;
                        mma16816(acc[mt][nt], ah[mt], bh[q]);   // A16 * Whi
                        mma16816(acc[mt][nt], ah[mt], bl[q]);   // A16 * Wlo
                    }
            }
        }
        __syncthreads();
    }

    // ---- epilogue: bias + mask, direct float2 stores ----
    const int rw = lane >> 2;
    const int cw = (lane & 3) * 2;
#pragma unroll
    for (int mt = 0; mt < 2; mt++) {
        int r = m0 + wm * 32 + mt * 16 + rw;
        bool z0 = (mask != nullptr) && (mask[r] != 0);
        bool z1 = (mask != nullptr) && (mask[r + 8] != 0);
#pragma unroll
        for (int nt = 0; nt < 8; nt++) {
            int cl = wn * 64 + nt * 8 + cw;
            float b0 = bias_s[cl], b1 = bias_s[cl + 1];
            float2 v0, v1;
            v0.x = z0 ? 0.f : acc[mt][nt][0] + b0;
            v0.y = z0 ? 0.f : acc[mt][nt][1] + b1;
            v1.x = z1 ? 0.f : acc[mt][nt][2] + b0;
            v1.y = z1 ? 0.f : acc[mt][nt][3] + b1;
            *(float2*)(C + (size_t)r * 256 + cl)       = v0;
            *(float2*)(C + (size_t)(r + 8) * 256 + cl) = v1;
        }
    }
}

// ---------------------------------------------------------------------------
// SIMT GEMM for the small N=128 projections (off / aw). fp32 exact.
// ---------------------------------------------------------------------------
#define SA_ 68
__global__ void gemm_bias_kernel(const float* __restrict__ A,
                                 const float* __restrict__ W,
                                 const float* __restrict__ bias,
                                 float* __restrict__ C,
                                 int M, int N, int K)
{
    __shared__ float As[32 * SA_];
    __shared__ float Bs[32 * SA_];

    const int m0 = blockIdx.x * 64;
    const int n0 = blockIdx.y * 64;
    const int t  = threadIdx.x;
    const int tm = t >> 4;
    const int tn = t & 15;

    float acc[4][4];
#pragma unroll
    for (int i = 0; i < 4; i++)
#pragma unroll
        for (int j = 0; j < 4; j++) acc[i][j] = 0.f;

    for (int k0 = 0; k0 < K; k0 += 32) {
#pragma unroll
        for (int u = 0; u < 2; u++) {
            int f   = t + u * 256;
            int row = f >> 3;
            int kc  = (f & 7) << 2;
            float4 a4 = *(const float4*)(A + (size_t)(m0 + row) * K + k0 + kc);
            As[(kc + 0) * SA_ + row] = a4.x;
            As[(kc + 1) * SA_ + row] = a4.y;
            As[(kc + 2) * SA_ + row] = a4.z;
            As[(kc + 3) * SA_ + row] = a4.w;
            float4 b4 = *(const float4*)(W + (size_t)(n0 + row) * K + k0 + kc);
            Bs[(kc + 0) * SA_ + row] = b4.x;
            Bs[(kc + 1) * SA_ + row] = b4.y;
            Bs[(kc + 2) * SA_ + row] = b4.z;
            Bs[(kc + 3) * SA_ + row] = b4.w;
        }
        __syncthreads();

#pragma unroll
        for (int k = 0; k < 32; k++) {
            float4 av = *(const float4*)(As + k * SA_ + tm * 4);
            float4 bv = *(const float4*)(Bs + k * SA_ + tn * 4);
            float ar[4] = {av.x, av.y, av.z, av.w};
            float br[4] = {bv.x, bv.y, bv.z, bv.w};
#pragma unroll
            for (int i = 0; i < 4; i++)
#pragma unroll
                for (int j = 0; j < 4; j++) acc[i][j] += ar[i] * br[j];
        }
        __syncthreads();
    }

#pragma unroll
    for (int i = 0; i < 4; i++) {
        int r = m0 + tm * 4 + i;
        int c = n0 + tn * 4;
        float4 o;
        o.x = acc[i][0] + bias[c + 0];
        o.y = acc[i][1] + bias[c + 1];
        o.z = acc[i][2] + bias[c + 2];
        o.w = acc[i][3] + bias[c + 3];
        *(float4*)(C + (size_t)r * N + c) = o;
    }
}

// ---------------------------------------------------------------------------
// Sampler v2 (passing R7 version, 87us).
// ---------------------------------------------------------------------------
__global__ __launch_bounds__(256)
void sample_kernel(const float* __restrict__ refwin,
                   float* __restrict__ awout)
{
    __shared__ float  sh_raw[128];
    __shared__ float  sh_off[128];
    __shared__ float2 sh_swlw[H_][64];
    __shared__ int4   sh_idx[512];
    __shared__ float4 sh_w[512];

    const int bq   = blockIdx.x;
    const int b    = bq >> 10;
    const int t    = threadIdx.x;
    const int h    = t >> 5;
    const int lane = t & 31;

    if (t < 128) sh_raw[t] = g_aw[(size_t)bq * 128 + t];
    else         sh_off[t - 128] = g_off[(size_t)bq * 128 + (t - 128)];
    __syncthreads();

    float e[2];
    int   aidx[2];
#pragma unroll
    for (int tgt = 0; tgt < 2; tgt++) {
        int n = lane + 32 * tgt;
        int l = n >> 4, kk = n & 15, ii = kk >> 2, jj = kk & 3;
        int a = ((ii >> 1) << 1) + (jj >> 1);
        aidx[tgt] = a;
        e[tgt] = sh_raw[h * 16 + l * 4 + a];
    }
    awout[(size_t)bq * 512 + h * 64 + lane]      = e[0];
    awout[(size_t)bq * 512 + h * 64 + lane + 32] = e[1];

    float m = fmaxf(e[0], e[1]);
#pragma unroll
    for (int o = 16; o > 0; o >>= 1) m = fmaxf(m, __shfl_xor_sync(0xffffffffu, m, o));
    float p0 = __expf(e[0] - m), p1 = __expf(e[1] - m);
    float s = p0 + p1;
#pragma unroll
    for (int o = 16; o > 0; o >>= 1) s += __shfl_xor_sync(0xffffffffu, s, o);
    float inv = 1.f / s;

#pragma unroll
    for (int tgt = 0; tgt < 2; tgt++) {
        int a = aidx[tgt];
        float r0 = sh_raw[h * 16 + 0 + a], r1 = sh_raw[h * 16 + 4 + a];
        float r2 = sh_raw[h * 16 + 8 + a], r3 = sh_raw[h * 16 + 12 + a];
        float m4 = fmaxf(fmaxf(r0, r1), fmaxf(r2, r3));
        float s4 = __expf(r0 - m4) + __expf(r1 - m4) + __expf(r2 - m4) + __expf(r3 - m4);
        float lw = __expf(e[tgt] - m4) / s4;
        float sw = (tgt == 0 ? p0 : p1) * inv;
        sh_swlw[h][lane + 32 * tgt] = make_float2(sw, lw);
    }

    const float rcx = refwin[bq * 4 + 0];
    const float rcy = refwin[bq * 4 + 1];
    const float rsx = refwin[bq * 4 + 2];
    const float rsy = refwin[bq * 4 + 3];

#pragma unroll
    for (int rep = 0; rep < 2; rep++) {
        int sidx = t + rep * 256;
        int hh = sidx >> 6;
        int n  = sidx & 63;
        int l  = n >> 4;
        int ii = (n >> 2) & 3;
        int jj = n & 3;

        float o0 = sh_off[hh * 16 + l * 4 + 0];
        float o1 = sh_off[hh * 16 + l * 4 + 1];
        float o2 = sh_off[hh * 16 + l * 4 + 2];
        float o3 = sh_off[hh * 16 + l * 4 + 3];
        float cx = rcx + o0 * 0.125f * rsx;
        float cy = rcy + o1 * 0.125f * rsy;
        float sx = fmaxf(rsx + o2 * 0.125f * rsx, 0.f);
        float sy = fmaxf(rsy + o3 * 0.125f * rsy, 0.f);

        int   Wl  = 128 >> l;
        float fW  = (float)Wl;
        int base  = (l == 0) ? 0 : (l == 1) ? 16384 : (l == 2) ? 20480 : 21504;

        float y   = (cy + ((float)ii - 1.5f) * 0.25f * sy) * fW - 0.5f;
        float x   = (cx + ((float)jj - 1.5f) * 0.25f * sx) * fW - 0.5f;
        float y0f = floorf(y);
        float x0f = floorf(x);
        float fy  = y - y0f;
        float fx  = x - x0f;
        int y0 = (int)y0f;
        int x0 = (int)x0f;
        bool vy0 = (y0 >= 0) && (y0 < Wl);
        bool vy1 = (y0 >= -1) && (y0 < Wl - 1);
        bool vx0 = (x0 >= 0) && (x0 < Wl);
        bool vx1 = (x0 >= -1) && (x0 < Wl - 1);
        int cy0 = min(max(y0, 0), Wl - 1);
        int cy1 = min(max(y0 + 1, 0), Wl - 1);
        int cx0 = min(max(x0, 0), Wl - 1);
        int cx1 = min(max(x0 + 1, 0), Wl - 1);

        int4 id;
        id.x = (base + cy0 * Wl + cx0) * 256;
        id.y = (base + cy0 * Wl + cx1) * 256;
        id.z = (base + cy1 * Wl + cx0) * 256;
        id.w = (base + cy1 * Wl + cx1) * 256;
        float4 w;
        w.x = (vx0 && vy0) ? (1.f - fx) * (1.f - fy) : 0.f;
        w.y = (vx1 && vy0) ? fx * (1.f - fy) : 0.f;
        w.z = (vx0 && vy1) ? (1.f - fx) * fy : 0.f;
        w.w = (vx1 && vy1) ? fx * fy : 0.f;
        sh_idx[sidx] = id;
        sh_w[sidx]   = w;
    }
    __syncthreads();

    const float* vb = g_v + (size_t)b * L2_ * 256 + h * 32 + lane;
    float acc_o = 0.f, acc_m = 0.f;

#pragma unroll 8
    for (int n = 0; n < 64; n++) {
        int4   id = sh_idx[h * 64 + n];
        float4 w  = sh_w[h * 64 + n];
        float val = w.x * vb[id.x] + w.y * vb[id.y]
                  + w.z * vb[id.z] + w.w * vb[id.w];
        float2 sl = sh_swlw[h][n];
        acc_o += sl.x * val;
        acc_m += sl.y * val;
    }

    const size_t od = (size_t)bq * D_ + h * HD_ + lane;
    g_outpre[od]  = acc_o;
    g_moutpre[od] = acc_m;
}

// ---------------------------------------------------------------------------
extern "C" void kernel_launch(void* const* d_in, const int* in_sizes, int n_in,
                              void* d_out, int out_size)
{
    const float* query = (const float*)d_in[0];
    const float* value = (const float*)d_in[1];
    const float* refw  = (const float*)d_in[2];
    const float* Wv    = (const float*)d_in[3];
    const float* bv    = (const float*)d_in[4];
    const float* Wo    = (const float*)d_in[5];
    const float* bo    = (const float*)d_in[6];
    const float* Wbox  = (const float*)d_in[7];
    const float* bbox  = (const float*)d_in[8];
    const float* Wattn = (const float*)d_in[9];
    const float* battn = (const float*)d_in[10];
    const unsigned char* vmask = (const unsigned char*)d_in[13];

    float* out   = (float*)d_out;
    float* mout  = out  + (size_t)NQ_ * D_;
    float* awout = mout + (size_t)NQ_ * D_;

    float *pv, *poff, *paw, *pop, *pmp;
    cudaGetSymbolAddress((void**)&pv,   g_v);
    cudaGetSymbolAddress((void**)&poff, g_off);
    cudaGetSymbolAddress((void**)&paw,  g_aw);
    cudaGetSymbolAddress((void**)&pop,  g_outpre);
    cudaGetSymbolAddress((void**)&pmp,  g_moutpre);
    __half *pwvh, *pwvl, *pwoh, *pwol;
    cudaGetSymbolAddress((void**)&pwvh, g_Wvh);
    cudaGetSymbolAddress((void**)&pwvl, g_Wvl);
    cudaGetSymbolAddress((void**)&pwoh, g_Woh);
    cudaGetSymbolAddress((void**)&pwol, g_Wol);

    // 0) W -> fp16 hi/lo
    prep_w_kernel<<<256, 256>>>(Wv, Wo);
    // 1) v = value @ Wv^T + bv, masked   (HMMA fp16 2-pass, single A pass)
    hmma_gemm_fp16<<<MV_ / 128, 512>>>(value, pwvh, pwvl, bv, pv, vmask);
    // 2) off = query @ Wbox^T + bbox
    gemm_bias_kernel<<<dim3(NQ_ / 64, 2), 256>>>(query, Wbox, bbox, poff,
                                                 NQ_, 128, D_);
    // 3) raw aw = query @ Wattn^T + battn
    gemm_bias_kernel<<<dim3(NQ_ / 64, 2), 256>>>(query, Wattn, battn, paw,
                                                 NQ_, 128, D_);
    // 4) softmaxes + sampling
    sample_kernel<<<NQ_, 256>>>(refw, awout);
    // 5) out / mout projections
    hmma_gemm_fp16<<<NQ_ / 128, 512>>>(pop, pwoh, pwol, bo, out, nullptr);
    hmma_gemm_fp16<<<NQ_ / 128, 512>>>(pmp, pwoh, pwol, bo, mout, nullptr);
}

// round 10
// speedup vs baseline: 1.2987x; 1.0852x over previous
#include <cuda_runtime.h>
#include <cuda_fp16.h>
#include <cstdint>
#include <cstring>

#define B_   4
#define L1_  1024
#define D_   256
#define H_   8
#define HD_  32
#define L_   4
#define L2_  21760
#define NQ_  (B_ * L1_)          // 4096
#define MV_  (B_ * L2_)          // 87040

// ---------------- scratch (static device memory; no allocs) ----------------
__device__ __half g_val16[(size_t)MV_ * D_];    // fp16(value)  (44.5 MB)
__device__ __half g_v16[(size_t)MV_ * D_];      // fp16 v = value @ Wv^T (44.5 MB)
__device__ float  g_qproj[(size_t)NQ_ * 256];   // [off | aw] fused projection
__device__ float  g_outpre[(size_t)NQ_ * D_];
__device__ float  g_moutpre[(size_t)NQ_ * D_];
__device__ __half g_Wvh[65536], g_Wvl[65536];   // Wv fp16 hi/lo
__device__ __half g_Woh[65536], g_Wol[65536];   // Wo fp16 hi/lo
__device__ __half g_Wqh[65536], g_Wql[65536];   // [Wbox;Wattn] fp16 hi/lo
__device__ float  g_bq[256];                    // [bbox | battn]

// ===========================================================================
// helpers
// ===========================================================================
__device__ __forceinline__ uint32_t h2_bits(__half2 h) {
    uint32_t u;
    memcpy(&u, &h, 4);
    return u;
}
__device__ __forceinline__ uint32_t smem_u32(const void* p) {
    uint32_t a;
    asm("{ .reg .u64 t; cvta.to.shared.u64 t, %1; cvt.u32.u64 %0, t; }"
        : "=r"(a) : "l"(p));
    return a;
}
__device__ __forceinline__ void ldmx4(uint32_t addr, uint32_t& r0, uint32_t& r1,
                                      uint32_t& r2, uint32_t& r3) {
    asm volatile("ldmatrix.sync.aligned.m8n8.x4.shared.b16 {%0,%1,%2,%3}, [%4];"
                 : "=r"(r0), "=r"(r1), "=r"(r2), "=r"(r3) : "r"(addr));
}
__device__ __forceinline__ void mma16816(float* d, const uint32_t* a,
                                         const uint32_t* b) {
    asm volatile("mma.sync.aligned.m16n8k16.row.col.f32.f16.f16.f32 "
                 "{%0,%1,%2,%3}, {%4,%5,%6,%7}, {%8,%9}, {%0,%1,%2,%3};"
                 : "+f"(d[0]), "+f"(d[1]), "+f"(d[2]), "+f"(d[3])
                 : "r"(a[0]), "r"(a[1]), "r"(a[2]), "r"(a[3]),
                   "r"(b[0]), "r"(b[1]));
}
#define CP_ASYNC16(dst, src) \
    asm volatile("cp.async.cg.shared.global [%0], [%1], 16;" :: "r"(dst), "l"(src))
#define CP_COMMIT() asm volatile("cp.async.commit_group;" ::: "memory")
#define CP_WAIT1()  asm volatile("cp.async.wait_group 1;" ::: "memory")
#define CP_WAIT0()  asm volatile("cp.async.wait_group 0;" ::: "memory")

// ---------------------------------------------------------------------------
// prep: weights -> fp16 hi/lo; fused q-projection weight/bias pack
// ---------------------------------------------------------------------------
__global__ void prep_w_kernel(const float* __restrict__ Wv,
                              const float* __restrict__ Wo,
                              const float* __restrict__ Wbox,
                              const float* __restrict__ Wattn,
                              const float* __restrict__ bbox,
                              const float* __restrict__ battn)
{
    int i = blockIdx.x * blockDim.x + threadIdx.x;   // 0..65535
    float v = Wv[i];
    __half h = __float2half_rn(v);
    g_Wvh[i] = h;
    g_Wvl[i] = __float2half_rn(v - __half2float(h));
    float o = Wo[i];
    __half ho = __float2half_rn(o);
    g_Woh[i] = ho;
    g_Wol[i] = __float2half_rn(o - __half2float(ho));
    int r = i >> 8, c = i & 255;
    float q = (r < 128) ? Wbox[r * 256 + c] : Wattn[(r - 128) * 256 + c];
    __half hq = __float2half_rn(q);
    g_Wqh[i] = hq;
    g_Wql[i] = __float2half_rn(q - __half2float(hq));
    if (i < 256) g_bq[i] = (i < 128) ? bbox[i] : battn[i - 128];
}

// value fp32 -> fp16 (4 elements/thread)
__global__ void prep_v_kernel(const float* __restrict__ value)
{
    size_t i4 = (size_t)blockIdx.x * blockDim.x + threadIdx.x;
    size_t base = i4 * 4;
    float4 v = *(const float4*)(value + base);
    *(__half2*)(g_val16 + base)     = __floats2half2_rn(v.x, v.y);
    *(__half2*)(g_val16 + base + 2) = __floats2half2_rn(v.z, v.w);
}

// ===========================================================================
// Value GEMM (cp.async 2-stage pipeline): C16[M,256] = A16[M,256] @ W^T + b,
// masked rows zeroed, fp16 output. Tile 128x256, 512 thr, BK=32.
// dynamic smem: 2 stages x (A 8KB + Bh 16KB + Bl 16KB) + bias 1KB = 82944 B
// ===========================================================================
#define STG_ 40960
__global__ __launch_bounds__(512)
void hmma_gemm_v(const __half* __restrict__ A16,
                 const __half* __restrict__ Wh,
                 const __half* __restrict__ Wl,
                 const float* __restrict__ bias,
                 __half* __restrict__ C,
                 const unsigned char* __restrict__ mask)
{
    extern __shared__ __align__(16) unsigned char dsm[];
    float* bias_s = (float*)(dsm + 2 * STG_);

    const int t    = threadIdx.x;
    const int wid  = t >> 5;
    const int lane = t & 31;
    const int wm   = wid & 3;
    const int wn   = wid >> 2;
    const int m0   = blockIdx.x * 128;
    const uint32_t base = smem_u32(dsm);

    if (t < 256) bias_s[t] = bias[t];

    float acc[2][8][4];
#pragma unroll
    for (int mt = 0; mt < 2; mt++)
#pragma unroll
        for (int nt = 0; nt < 8; nt++)
#pragma unroll
            for (int i = 0; i < 4; i++) acc[mt][nt][i] = 0.f;

    // stage loader: A(128x32) + Wh/Wl(256x32) as 16B cp.async
    auto stage_load = [&](int stage, int k0) {
        uint32_t sb = base + stage * STG_;
        {
            int r   = t >> 2;
            int c16 = t & 3;
            uint32_t d = sb + r * 64 + ((c16 ^ ((r >> 1) & 3)) * 16);
            CP_ASYNC16(d, A16 + (size_t)(m0 + r) * 256 + k0 + c16 * 8);
        }
#pragma unroll
        for (int u = 0; u < 2; u++) {
            int f   = t + u * 512;
            int r   = f >> 2;
            int c16 = f & 3;
            uint32_t off = r * 64 + ((c16 ^ ((r >> 1) & 3)) * 16);
            CP_ASYNC16(sb + 8192 + off,  Wh + (size_t)r * 256 + k0 + c16 * 8);
            CP_ASYNC16(sb + 24576 + off, Wl + (size_t)r * 256 + k0 + c16 * 8);
        }
        CP_COMMIT();
    };

    stage_load(0, 0);

    for (int ch = 0; ch < 8; ch++) {
        if (ch < 7) { stage_load((ch + 1) & 1, (ch + 1) * 32); CP_WAIT1(); }
        else        { CP_WAIT0(); }
        __syncthreads();

        const uint32_t sb = base + (ch & 1) * STG_;
        const uint32_t uA  = sb;
        const uint32_t uBh = sb + 8192;
        const uint32_t uBl = sb + 24576;

#pragma unroll
        for (int s = 0; s < 2; s++) {
            uint32_t ah[2][4];
#pragma unroll
            for (int mt = 0; mt < 2; mt++) {
                int row  = wm * 32 + mt * 16 + (lane & 15);
                int unit = s * 2 + (lane >> 4);
                ldmx4(uA + row * 64 + (unit ^ ((row >> 1) & 3)) * 16,
                      ah[mt][0], ah[mt][1], ah[mt][2], ah[mt][3]);
            }
#pragma unroll
            for (int half = 0; half < 2; half++) {
                uint32_t bh[4][2], bl[4][2];
#pragma unroll
                for (int p = 0; p < 2; p++) {
                    int pp   = half * 2 + p;
                    int nrow = wn * 64 + pp * 16 + (lane & 7) + (((lane >> 4) & 1) << 3);
                    int unit = s * 2 + ((lane >> 3) & 1);
                    uint32_t off = nrow * 64 + (unit ^ ((nrow >> 1) & 3)) * 16;
                    ldmx4(uBh + off, bh[p*2][0], bh[p*2][1], bh[p*2+1][0], bh[p*2+1][1]);
                    ldmx4(uBl + off, bl[p*2][0], bl[p*2][1], bl[p*2+1][0], bl[p*2+1][1]);
                }
#pragma unroll
                for (int mt = 0; mt < 2; mt++)
#pragma unroll
                    for (int q = 0; q < 4; q++) {
                        int nt = half * 4 + q;
                        mma16816(acc[mt][nt], ah[mt], bh[q]);
                        mma16816(acc[mt][nt], ah[mt], bl[q]);
                    }
            }
        }
        __syncthreads();
    }

    // epilogue: bias + mask, fp16 stores
    const int rw = lane >> 2;
    const int cw = (lane & 3) * 2;
#pragma unroll
    for (int mt = 0; mt < 2; mt++) {
        int r = m0 + wm * 32 + mt * 16 + rw;
        bool z0 = mask[r] != 0;
        bool z1 = mask[r + 8] != 0;
#pragma unroll
        for (int nt = 0; nt < 8; nt++) {
            int cl = wn * 64 + nt * 8 + cw;
            float b0 = bias_s[cl], b1 = bias_s[cl + 1];
            __half2 v0 = __floats2half2_rn(z0 ? 0.f : acc[mt][nt][0] + b0,
                                           z0 ? 0.f : acc[mt][nt][1] + b1);
            __half2 v1 = __floats2half2_rn(z1 ? 0.f : acc[mt][nt][2] + b0,
                                           z1 ? 0.f : acc[mt][nt][3] + b1);
            *(__half2*)(C + (size_t)r * 256 + cl)       = v0;
            *(__half2*)(C + (size_t)(r + 8) * 256 + cl) = v1;
        }
    }
}

// ===========================================================================
// fp32-A HMMA GEMM (for q-projection and out/mout): C[M,256] fp32.
// Same structure as passing R9 kernel.
// ===========================================================================
__global__ __launch_bounds__(512)
void hmma_gemm_fp16(const float* __restrict__ A,
                    const __half* __restrict__ Wh,
                    const __half* __restrict__ Wl,
                    const float* __restrict__ bias,
                    float* __restrict__ C)
{
    __shared__ __align__(16) unsigned char smA [128 * 64];
    __shared__ __align__(16) unsigned char smBh[256 * 64];
    __shared__ __align__(16) unsigned char smBl[256 * 64];
    __shared__ float bias_s[256];

    const int t    = threadIdx.x;
    const int wid  = t >> 5;
    const int lane = t & 31;
    const int wm   = wid & 3;
    const int wn   = wid >> 2;
    const int m0   = blockIdx.x * 128;

    if (t < 256) bias_s[t] = bias[t];

    float acc[2][8][4];
#pragma unroll
    for (int mt = 0; mt < 2; mt++)
#pragma unroll
        for (int nt = 0; nt < 8; nt++)
#pragma unroll
            for (int i = 0; i < 4; i++) acc[mt][nt][i] = 0.f;

    const uint32_t uA  = smem_u32(smA);
    const uint32_t uBh = smem_u32(smBh);
    const uint32_t uBl = smem_u32(smBl);

    for (int k0 = 0; k0 < 256; k0 += 32) {
        {
            int r  = t >> 2;
            int c4 = t & 3;
            const float* src = A + (size_t)(m0 + r) * 256 + k0 + c4 * 8;
            float4 v0 = *(const float4*)(src);
            float4 v1 = *(const float4*)(src + 4);
            uint4 u;
            u.x = h2_bits(__floats2half2_rn(v0.x, v0.y));
            u.y = h2_bits(__floats2half2_rn(v0.z, v0.w));
            u.z = h2_bits(__floats2half2_rn(v1.x, v1.y));
            u.w = h2_bits(__floats2half2_rn(v1.z, v1.w));
            *(uint4*)(smA + r * 64 + (c4 ^ ((r >> 1) & 3)) * 16) = u;
        }
#pragma unroll
        for (int u = 0; u < 2; u++) {
            int f   = t + u * 512;
            int r   = f >> 2;
            int c16 = f & 3;
            uint32_t dst = r * 64 + (c16 ^ ((r >> 1) & 3)) * 16;
            *(uint4*)(smBh + dst) = *(const uint4*)(Wh + (size_t)r * 256 + k0 + c16 * 8);
            *(uint4*)(smBl + dst) = *(const uint4*)(Wl + (size_t)r * 256 + k0 + c16 * 8);
        }
        __syncthreads();

#pragma unroll
        for (int s = 0; s < 2; s++) {
            uint32_t ah[2][4];
#pragma unroll
            for (int mt = 0; mt < 2; mt++) {
                int row  = wm * 32 + mt * 16 + (lane & 15);
                int unit = s * 2 + (lane >> 4);
                ldmx4(uA + row * 64 + (unit ^ ((row >> 1) & 3)) * 16,
                      ah[mt][0], ah[mt][1], ah[mt][2], ah[mt][3]);
            }
#pragma unroll
            for (int half = 0; half < 2; half++) {
                uint32_t bh[4][2], bl[4][2];
#pragma unroll
                for (int p = 0; p < 2; p++) {
                    int pp   = half * 2 + p;
                    int nrow = wn * 64 + pp * 16 + (lane & 7) + (((lane >> 4) & 1) << 3);
                    int unit = s * 2 + ((lane >> 3) & 1);
                    uint32_t off = nrow * 64 + (unit ^ ((nrow >> 1) & 3)) * 16;
                    ldmx4(uBh + off, bh[p*2][0], bh[p*2][1], bh[p*2+1][0], bh[p*2+1][1]);
                    ldmx4(uBl + off, bl[p*2][0], bl[p*2][1], bl[p*2+1][0], bl[p*2+1][1]);
                }
#pragma unroll
                for (int mt = 0; mt < 2; mt++)
#pragma unroll
                    for (int q = 0; q < 4; q++) {
                        int nt = half * 4 + q;
                        mma16816(acc[mt][nt], ah[mt], bh[q]);
                        mma16816(acc[mt][nt], ah[mt], bl[q]);
                    }
            }
        }
        __syncthreads();
    }

    const int rw = lane >> 2;
    const int cw = (lane & 3) * 2;
#pragma unroll
    for (int mt = 0; mt < 2; mt++) {
        int r = m0 + wm * 32 + mt * 16 + rw;
#pragma unroll
        for (int nt = 0; nt < 8; nt++) {
            int cl = wn * 64 + nt * 8 + cw;
            float b0 = bias_s[cl], b1 = bias_s[cl + 1];
            float2 v0 = make_float2(acc[mt][nt][0] + b0, acc[mt][nt][1] + b1);
            float2 v1 = make_float2(acc[mt][nt][2] + b0, acc[mt][nt][3] + b1);
            *(float2*)(C + (size_t)r * 256 + cl)       = v0;
            *(float2*)(C + (size_t)(r + 8) * 256 + cl) = v1;
        }
    }
}

// ---------------------------------------------------------------------------
// Sampler: reads fused g_qproj [off|aw], gathers fp16 g_v16.
// ---------------------------------------------------------------------------
__global__ __launch_bounds__(256)
void sample_kernel(const float* __restrict__ refwin,
                   float* __restrict__ awout)
{
    __shared__ float  sh_raw[128];
    __shared__ float  sh_off[128];
    __shared__ float2 sh_swlw[H_][64];
    __shared__ int4   sh_idx[512];
    __shared__ float4 sh_w[512];

    const int bq   = blockIdx.x;
    const int b    = bq >> 10;
    const int t    = threadIdx.x;
    const int h    = t >> 5;
    const int lane = t & 31;

    if (t < 128) sh_off[t] = g_qproj[(size_t)bq * 256 + t];
    else         sh_raw[t - 128] = g_qproj[(size_t)bq * 256 + t];
    __syncthreads();

    float e[2];
    int   aidx[2];
#pragma unroll
    for (int tgt = 0; tgt < 2; tgt++) {
        int n = lane + 32 * tgt;
        int l = n >> 4, kk = n & 15, ii = kk >> 2, jj = kk & 3;
        int a = ((ii >> 1) << 1) + (jj >> 1);
        aidx[tgt] = a;
        e[tgt] = sh_raw[h * 16 + l * 4 + a];
    }
    awout[(size_t)bq * 512 + h * 64 + lane]      = e[0];
    awout[(size_t)bq * 512 + h * 64 + lane + 32] = e[1];

    float m = fmaxf(e[0], e[1]);
#pragma unroll
    for (int o = 16; o > 0; o >>= 1) m = fmaxf(m, __shfl_xor_sync(0xffffffffu, m, o));
    float p0 = __expf(e[0] - m), p1 = __expf(e[1] - m);
    float s = p0 + p1;
#pragma unroll
    for (int o = 16; o > 0; o >>= 1) s += __shfl_xor_sync(0xffffffffu, s, o);
    float inv = 1.f / s;

#pragma unroll
    for (int tgt = 0; tgt < 2; tgt++) {
        int a = aidx[tgt];
        float r0 = sh_raw[h * 16 + 0 + a], r1 = sh_raw[h * 16 + 4 + a];
        float r2 = sh_raw[h * 16 + 8 + a], r3 = sh_raw[h * 16 + 12 + a];
        float m4 = fmaxf(fmaxf(r0, r1), fmaxf(r2, r3));
        float s4 = __expf(r0 - m4) + __expf(r1 - m4) + __expf(r2 - m4) + __expf(r3 - m4);
        float lw = __expf(e[tgt] - m4) / s4;
        float sw = (tgt == 0 ? p0 : p1) * inv;
        sh_swlw[h][lane + 32 * tgt] = make_float2(sw, lw);
    }

    const float rcx = refwin[bq * 4 + 0];
    const float rcy = refwin[bq * 4 + 1];
    const float rsx = refwin[bq * 4 + 2];
    const float rsy = refwin[bq * 4 + 3];

#pragma unroll
    for (int rep = 0; rep < 2; rep++) {
        int sidx = t + rep * 256;
        int hh = sidx >> 6;
        int n  = sidx & 63;
        int l  = n >> 4;
        int ii = (n >> 2) & 3;
        int jj = n & 3;

        float o0 = sh_off[hh * 16 + l * 4 + 0];
        float o1 = sh_off[hh * 16 + l * 4 + 1];
        float o2 = sh_off[hh * 16 + l * 4 + 2];
        float o3 = sh_off[hh * 16 + l * 4 + 3];
        float cx = rcx + o0 * 0.125f * rsx;
        float cy = rcy + o1 * 0.125f * rsy;
        float sx = fmaxf(rsx + o2 * 0.125f * rsx, 0.f);
        float sy = fmaxf(rsy + o3 * 0.125f * rsy, 0.f);

        int   Wl  = 128 >> l;
        float fW  = (float)Wl;
        int base  = (l == 0) ? 0 : (l == 1) ? 16384 : (l == 2) ? 20480 : 21504;

        float y   = (cy + ((float)ii - 1.5f) * 0.25f * sy) * fW - 0.5f;
        float x   = (cx + ((float)jj - 1.5f) * 0.25f * sx) * fW - 0.5f;
        float y0f = floorf(y);
        float x0f = floorf(x);
        float fy  = y - y0f;
        float fx  = x - x0f;
        int y0 = (int)y0f;
        int x0 = (int)x0f;
        bool vy0 = (y0 >= 0) && (y0 < Wl);
        bool vy1 = (y0 >= -1) && (y0 < Wl - 1);
        bool vx0 = (x0 >= 0) && (x0 < Wl);
        bool vx1 = (x0 >= -1) && (x0 < Wl - 1);
        int cy0 = min(max(y0, 0), Wl - 1);
        int cy1 = min(max(y0 + 1, 0), Wl - 1);
        int cx0 = min(max(x0, 0), Wl - 1);
        int cx1 = min(max(x0 + 1, 0), Wl - 1);

        int4 id;
        id.x = (base + cy0 * Wl + cx0) * 256;
        id.y = (base + cy0 * Wl + cx1) * 256;
        id.z = (base + cy1 * Wl + cx0) * 256;
        id.w = (base + cy1 * Wl + cx1) * 256;
        float4 w;
        w.x = (vx0 && vy0) ? (1.f - fx) * (1.f - fy) : 0.f;
        w.y = (vx1 && vy0) ? fx * (1.f - fy) : 0.f;
        w.z = (vx0 && vy1) ? (1.f - fx) * fy : 0.f;
        w.w = (vx1 && vy1) ? fx * fy : 0.f;
        sh_idx[sidx] = id;
        sh_w[sidx]   = w;
    }
    __syncthreads();

    const __half* vb = g_v16 + (size_t)b * L2_ * 256 + h * 32 + lane;
    float acc_o = 0.f, acc_m = 0.f;

#pragma unroll 8
    for (int n = 0; n < 64; n++) {
        int4   id = sh_idx[h * 64 + n];
        float4 w  = sh_w[h * 64 + n];
        float val = w.x * __half2float(vb[id.x]) + w.y * __half2float(vb[id.y])
                  + w.z * __half2float(vb[id.z]) + w.w * __half2float(vb[id.w]);
        float2 sl = sh_swlw[h][n];
        acc_o += sl.x * val;
        acc_m += sl.y * val;
    }

    const size_t od = (size_t)bq * D_ + h * HD_ + lane;
    g_outpre[od]  = acc_o;
    g_moutpre[od] = acc_m;
}

// ---------------------------------------------------------------------------
extern "C" void kernel_launch(void* const* d_in, const int* in_sizes, int n_in,
                              void* d_out, int out_size)
{
    const float* query = (const float*)d_in[0];
    const float* value = (const float*)d_in[1];
    const float* refw  = (const float*)d_in[2];
    const float* Wv    = (const float*)d_in[3];
    const float* bv    = (const float*)d_in[4];
    const float* Wo    = (const float*)d_in[5];
    const float* bo    = (const float*)d_in[6];
    const float* Wbox  = (const float*)d_in[7];
    const float* bbox  = (const float*)d_in[8];
    const float* Wattn = (const float*)d_in[9];
    const float* battn = (const float*)d_in[10];
    const unsigned char* vmask = (const unsigned char*)d_in[13];

    float* out   = (float*)d_out;
    float* mout  = out  + (size_t)NQ_ * D_;
    float* awout = mout + (size_t)NQ_ * D_;

    float *pqp, *pop, *pmp, *pbq;
    __half *pval16, *pv16, *pwvh, *pwvl, *pwoh, *pwol, *pwqh, *pwql;
    cudaGetSymbolAddress((void**)&pval16, g_val16);
    cudaGetSymbolAddress((void**)&pv16,   g_v16);
    cudaGetSymbolAddress((void**)&pqp,    g_qproj);
    cudaGetSymbolAddress((void**)&pop,    g_outpre);
    cudaGetSymbolAddress((void**)&pmp,    g_moutpre);
    cudaGetSymbolAddress((void**)&pwvh,   g_Wvh);
    cudaGetSymbolAddress((void**)&pwvl,   g_Wvl);
    cudaGetSymbolAddress((void**)&pwoh,   g_Woh);
    cudaGetSymbolAddress((void**)&pwol,   g_Wol);
    cudaGetSymbolAddress((void**)&pwqh,   g_Wqh);
    cudaGetSymbolAddress((void**)&pwql,   g_Wql);
    cudaGetSymbolAddress((void**)&pbq,    g_bq);

    cudaFuncSetAttribute(hmma_gemm_v,
                         cudaFuncAttributeMaxDynamicSharedMemorySize, 2 * STG_ + 1024);

    // 0) prep: weights hi/lo + fused q weights; value -> fp16
    prep_w_kernel<<<256, 256>>>(Wv, Wo, Wbox, Wattn, bbox, battn);
    prep_v_kernel<<<MV_ * D_ / 4 / 256, 256>>>(value);
    // 1) fused q projection: g_qproj = query @ [Wbox;Wattn]^T + [bbox;battn]
    hmma_gemm_fp16<<<NQ_ / 128, 512>>>(query, pwqh, pwql, pbq, pqp);
    // 2) v = value @ Wv^T + bv (fp16 out, masked), cp.async pipelined
    hmma_gemm_v<<<MV_ / 128, 512, 2 * STG_ + 1024>>>(pval16, pwvh, pwvl, bv,
                                                     pv16, vmask);
    // 3) softmaxes + sampling
    sample_kernel<<<NQ_, 256>>>(refw, awout);
    // 4) out / mout projections
    hmma_gemm_fp16<<<NQ_ / 128, 512>>>(pop, pwoh, pwol, bo, out);
    hmma_gemm_fp16<<<NQ_ / 128, 512>>>(pmp, pwoh, pwol, bo, mout);
}

// round 12
// speedup vs baseline: 1.6148x; 1.2434x over previous
#include <cuda_runtime.h>
#include <cuda_fp16.h>
#include <cstdint>
#include <cstring>

#define B_   4
#define L1_  1024
#define D_   256
#define H_   8
#define HD_  32
#define L_   4
#define L2_  21760
#define NQ_  (B_ * L1_)          // 4096
#define MV_  (B_ * L2_)          // 87040

// ---------------- scratch (static device memory; no allocs) ----------------
__device__ __half g_val16[(size_t)MV_ * D_];    // fp16(value)  (44.5 MB)
__device__ __half g_v16[(size_t)MV_ * D_];      // fp16 v = value @ Wv^T (44.5 MB)
__device__ float  g_qproj[(size_t)NQ_ * 256];   // [off | aw] fused projection
__device__ float  g_outpre[(size_t)NQ_ * D_];
__device__ float  g_moutpre[(size_t)NQ_ * D_];
__device__ __half g_Wvh[65536];                 // Wv fp16 (single pass)
__device__ __half g_Woh[65536], g_Wol[65536];   // Wo fp16 hi/lo
__device__ __half g_Wqh[65536], g_Wql[65536];   // [Wbox;Wattn] fp16 hi/lo
__device__ float  g_bq[256];                    // [bbox | battn]

// ===========================================================================
// helpers
// ===========================================================================
__device__ __forceinline__ uint32_t h2_bits(__half2 h) {
    uint32_t u;
    memcpy(&u, &h, 4);
    return u;
}
__device__ __forceinline__ uint32_t smem_u32(const void* p) {
    uint32_t a;
    asm("{ .reg .u64 t; cvta.to.shared.u64 t, %1; cvt.u32.u64 %0, t; }"
        : "=r"(a) : "l"(p));
    return a;
}
__device__ __forceinline__ void ldmx4(uint32_t addr, uint32_t& r0, uint32_t& r1,
                                      uint32_t& r2, uint32_t& r3) {
    asm volatile("ldmatrix.sync.aligned.m8n8.x4.shared.b16 {%0,%1,%2,%3}, [%4];"
                 : "=r"(r0), "=r"(r1), "=r"(r2), "=r"(r3) : "r"(addr));
}
__device__ __forceinline__ void mma16816(float* d, const uint32_t* a,
                                         const uint32_t* b) {
    asm volatile("mma.sync.aligned.m16n8k16.row.col.f32.f16.f16.f32 "
                 "{%0,%1,%2,%3}, {%4,%5,%6,%7}, {%8,%9}, {%0,%1,%2,%3};"
                 : "+f"(d[0]), "+f"(d[1]), "+f"(d[2]), "+f"(d[3])
                 : "r"(a[0]), "r"(a[1]), "r"(a[2]), "r"(a[3]),
                   "r"(b[0]), "r"(b[1]));
}
#define CP_ASYNC16(dst, src) \
    asm volatile("cp.async.cg.shared.global [%0], [%1], 16;" :: "r"(dst), "l"(src))
#define CP_COMMIT() asm volatile("cp.async.commit_group;" ::: "memory")
#define CP_WAIT2()  asm volatile("cp.async.wait_group 2;" ::: "memory")

// ---------------------------------------------------------------------------
// prep: weights -> fp16 (Wv single, Wo/[Wbox;Wattn] hi/lo); bias pack
// ---------------------------------------------------------------------------
__global__ void prep_w_kernel(const float* __restrict__ Wv,
                              const float* __restrict__ Wo,
                              const float* __restrict__ Wbox,
                              const float* __restrict__ Wattn,
                              const float* __restrict__ bbox,
                              const float* __restrict__ battn)
{
    int i = blockIdx.x * blockDim.x + threadIdx.x;   // 0..65535
    g_Wvh[i] = __float2half_rn(Wv[i]);
    float o = Wo[i];
    __half ho = __float2half_rn(o);
    g_Woh[i] = ho;
    g_Wol[i] = __float2half_rn(o - __half2float(ho));
    int r = i >> 8, c = i & 255;
    float q = (r < 128) ? Wbox[r * 256 + c] : Wattn[(r - 128) * 256 + c];
    __half hq = __float2half_rn(q);
    g_Wqh[i] = hq;
    g_Wql[i] = __float2half_rn(q - __half2float(hq));
    if (i < 256) g_bq[i] = (i < 128) ? bbox[i] : battn[i - 128];
}

// value fp32 -> fp16 (4 elements/thread)
__global__ void prep_v_kernel(const float* __restrict__ value)
{
    size_t i4 = (size_t)blockIdx.x * blockDim.x + threadIdx.x;
    size_t base = i4 * 4;
    float4 v = *(const float4*)(value + base);
    *(__half2*)(g_val16 + base)     = __floats2half2_rn(v.x, v.y);
    *(__half2*)(g_val16 + base + 2) = __floats2half2_rn(v.z, v.w);
}

// ===========================================================================
// Value GEMM: C16[M,256] = A16[M,256] @ Wh^T + b, masked rows zeroed.
// A tile (128x256, 64KB) fully smem-resident; W single-pass fp16 streamed
// through a 4-stage (4x16KB) cp.async pipeline. 512 thr, warp tile 32x64.
// dyn smem = 64K (A) + 64K (W stages) + 1K (bias) = 132096 B
// ===========================================================================
#define VA_SZ   65536
#define VW_STG  16384
__global__ __launch_bounds__(512)
void hmma_gemm_v(const __half* __restrict__ A16,
                 const __half* __restrict__ Wh,
                 const float* __restrict__ bias,
                 __half* __restrict__ C,
                 const unsigned char* __restrict__ mask)
{
    extern __shared__ __align__(16) unsigned char dsm[];
    float* bias_s = (float*)(dsm + VA_SZ + 4 * VW_STG);

    const int t    = threadIdx.x;
    const int wid  = t >> 5;
    const int lane = t & 31;
    const int wm   = wid & 3;
    const int wn   = wid >> 2;
    const int m0   = blockIdx.x * 128;
    const uint32_t base  = smem_u32(dsm);
    const uint32_t wbase = base + VA_SZ;

    if (t < 256) bias_s[t] = bias[t];

    float acc[2][8][4];
#pragma unroll
    for (int mt = 0; mt < 2; mt++)
#pragma unroll
        for (int nt = 0; nt < 8; nt++)
#pragma unroll
            for (int i = 0; i < 4; i++) acc[mt][nt][i] = 0.f;

    // W stage loader: 256 rows x 32 cols fp16 (16KB), 2 x 16B per thread
    auto load_w = [&](int stage, int ch) {
        uint32_t sb = wbase + stage * VW_STG;
#pragma unroll
        for (int u = 0; u < 2; u++) {
            int f   = t + u * 512;
            int r   = f >> 2;
            int c16 = f & 3;
            uint32_t off = r * 64 + ((c16 ^ ((r >> 1) & 3)) * 16);
            CP_ASYNC16(sb + off, Wh + (size_t)r * 256 + ch * 32 + c16 * 8);
        }
    };

    // prologue: FULL A tile (128x256 fp16 = 64KB; 8 x 16B per thread)
    {
#pragma unroll
        for (int u = 0; u < 8; u++) {
            int f   = t + u * 512;    // 0..4095
            int r   = f >> 5;         // 0..127
            int c16 = f & 31;         // 16B unit within row (0..31)
            int ch  = c16 >> 2;       // k-chunk 0..7
            int cu  = c16 & 3;        // unit within chunk
            uint32_t dst = base + ch * 8192 + r * 64 + ((cu ^ ((r >> 1) & 3)) * 16);
            CP_ASYNC16(dst, A16 + (size_t)(m0 + r) * 256 + c16 * 8);
        }
        load_w(0, 0);
        CP_COMMIT();              // group 0 = A + W0
        load_w(1, 1); CP_COMMIT();// group 1
        load_w(2, 2); CP_COMMIT();// group 2
    }

    for (int ch = 0; ch < 8; ch++) {
        CP_WAIT2();               // groups 0..ch complete
        __syncthreads();
        if (ch + 3 < 8) load_w((ch + 3) & 3, ch + 3);
        CP_COMMIT();              // keep group counting uniform

        const uint32_t uA = base + ch * 8192;
        const uint32_t uB = wbase + (ch & 3) * VW_STG;

#pragma unroll
        for (int s = 0; s < 2; s++) {
            uint32_t ah[2][4];
#pragma unroll
            for (int mt = 0; mt < 2; mt++) {
                int row  = wm * 32 + mt * 16 + (lane & 15);
                int unit = s * 2 + (lane >> 4);
                ldmx4(uA + row * 64 + (unit ^ ((row >> 1) & 3)) * 16,
                      ah[mt][0], ah[mt][1], ah[mt][2], ah[mt][3]);
            }
#pragma unroll
            for (int half = 0; half < 2; half++) {
                uint32_t bh[4][2];
#pragma unroll
                for (int p = 0; p < 2; p++) {
                    int pp   = half * 2 + p;
                    int nrow = wn * 64 + pp * 16 + (lane & 7) + (((lane >> 4) & 1) << 3);
                    int unit = s * 2 + ((lane >> 3) & 1);
                    uint32_t off = nrow * 64 + (unit ^ ((nrow >> 1) & 3)) * 16;
                    ldmx4(uB + off, bh[p*2][0], bh[p*2][1], bh[p*2+1][0], bh[p*2+1][1]);
                }
#pragma unroll
                for (int mt = 0; mt < 2; mt++)
#pragma unroll
                    for (int q = 0; q < 4; q++)
                        mma16816(acc[mt][half * 4 + q], ah[mt], bh[q]);
            }
        }
        __syncthreads();
    }

    // epilogue: bias + mask, fp16 stores
    const int rw = lane >> 2;
    const int cw = (lane & 3) * 2;
#pragma unroll
    for (int mt = 0; mt < 2; mt++) {
        int r = m0 + wm * 32 + mt * 16 + rw;
        bool z0 = mask[r] != 0;
        bool z1 = mask[r + 8] != 0;
#pragma unroll
        for (int nt = 0; nt < 8; nt++) {
            int cl = wn * 64 + nt * 8 + cw;
            float b0 = bias_s[cl], b1 = bias_s[cl + 1];
            __half2 v0 = __floats2half2_rn(z0 ? 0.f : acc[mt][nt][0] + b0,
                                           z0 ? 0.f : acc[mt][nt][1] + b1);
            __half2 v1 = __floats2half2_rn(z1 ? 0.f : acc[mt][nt][2] + b0,
                                           z1 ? 0.f : acc[mt][nt][3] + b1);
            *(__half2*)(C + (size_t)r * 256 + cl)       = v0;
            *(__half2*)(C + (size_t)(r + 8) * 256 + cl) = v1;
        }
    }
}

// ===========================================================================
// fp32-A 2-pass HMMA GEMM (q-projection, out/mout): C[M,256] fp32.
// blockIdx.y selects (A0,C0) or (A1,C1) — fuses out+mout into one launch.
// ===========================================================================
__global__ __launch_bounds__(512)
void hmma_gemm_fp16(const float* __restrict__ A0,
                    const float* __restrict__ A1,
                    const __half* __restrict__ Wh,
                    const __half* __restrict__ Wl,
                    const float* __restrict__ bias,
                    float* __restrict__ C0,
                    float* __restrict__ C1)
{
    __shared__ __align__(16) unsigned char smA [128 * 64];
    __shared__ __align__(16) unsigned char smBh[256 * 64];
    __shared__ __align__(16) unsigned char smBl[256 * 64];
    __shared__ float bias_s[256];

    const float* A = blockIdx.y ? A1 : A0;
    float*       C = blockIdx.y ? C1 : C0;

    const int t    = threadIdx.x;
    const int wid  = t >> 5;
    const int lane = t & 31;
    const int wm   = wid & 3;
    const int wn   = wid >> 2;
    const int m0   = blockIdx.x * 128;

    if (t < 256) bias_s[t] = bias[t];

    float acc[2][8][4];
#pragma unroll
    for (int mt = 0; mt < 2; mt++)
#pragma unroll
        for (int nt = 0; nt < 8; nt++)
#pragma unroll
            for (int i = 0; i < 4; i++) acc[mt][nt][i] = 0.f;

    const uint32_t uA  = smem_u32(smA);
    const uint32_t uBh = smem_u32(smBh);
    const uint32_t uBl = smem_u32(smBl);

    for (int k0 = 0; k0 < 256; k0 += 32) {
        {
            int r  = t >> 2;
            int c4 = t & 3;
            const float* src = A + (size_t)(m0 + r) * 256 + k0 + c4 * 8;
            float4 v0 = *(const float4*)(src);
            float4 v1 = *(const float4*)(src + 4);
            uint4 u;
            u.x = h2_bits(__floats2half2_rn(v0.x, v0.y));
            u.y = h2_bits(__floats2half2_rn(v0.z, v0.w));
            u.z = h2_bits(__floats2half2_rn(v1.x, v1.y));
            u.w = h2_bits(__floats2half2_rn(v1.z, v1.w));
            *(uint4*)(smA + r * 64 + (c4 ^ ((r >> 1) & 3)) * 16) = u;
        }
#pragma unroll
        for (int u = 0; u < 2; u++) {
            int f   = t + u * 512;
            int r   = f >> 2;
            int c16 = f & 3;
            uint32_t dst = r * 64 + (c16 ^ ((r >> 1) & 3)) * 16;
            *(uint4*)(smBh + dst) = *(const uint4*)(Wh + (size_t)r * 256 + k0 + c16 * 8);
            *(uint4*)(smBl + dst) = *(const uint4*)(Wl + (size_t)r * 256 + k0 + c16 * 8);
        }
        __syncthreads();

#pragma unroll
        for (int s = 0; s < 2; s++) {
            uint32_t ah[2][4];
#pragma unroll
            for (int mt = 0; mt < 2; mt++) {
                int row  = wm * 32 + mt * 16 + (lane & 15);
                int unit = s * 2 + (lane >> 4);
                ldmx4(uA + row * 64 + (unit ^ ((row >> 1) & 3)) * 16,
                      ah[mt][0], ah[mt][1], ah[mt][2], ah[mt][3]);
            }
#pragma unroll
            for (int half = 0; half < 2; half++) {
                uint32_t bh[4][2], bl[4][2];
#pragma unroll
                for (int p = 0; p < 2; p++) {
                    int pp   = half * 2 + p;
                    int nrow = wn * 64 + pp * 16 + (lane & 7) + (((lane >> 4) & 1) << 3);
                    int unit = s * 2 + ((lane >> 3) & 1);
                    uint32_t off = nrow * 64 + (unit ^ ((nrow >> 1) & 3)) * 16;
                    ldmx4(uBh + off, bh[p*2][0], bh[p*2][1], bh[p*2+1][0], bh[p*2+1][1]);
                    ldmx4(uBl + off, bl[p*2][0], bl[p*2][1], bl[p*2+1][0], bl[p*2+1][1]);
                }
#pragma unroll
                for (int mt = 0; mt < 2; mt++)
#pragma unroll
                    for (int q = 0; q < 4; q++) {
                        int nt = half * 4 + q;
                        mma16816(acc[mt][nt], ah[mt], bh[q]);
                        mma16816(acc[mt][nt], ah[mt], bl[q]);
                    }
            }
        }
        __syncthreads();
    }

    const int rw = lane >> 2;
    const int cw = (lane & 3) * 2;
#pragma unroll
    for (int mt = 0; mt < 2; mt++) {
        int r = m0 + wm * 32 + mt * 16 + rw;
#pragma unroll
        for (int nt = 0; nt < 8; nt++) {
            int cl = wn * 64 + nt * 8 + cw;
            float b0 = bias_s[cl], b1 = bias_s[cl + 1];
            float2 v0 = make_float2(acc[mt][nt][0] + b0, acc[mt][nt][1] + b1);
            float2 v1 = make_float2(acc[mt][nt][2] + b0, acc[mt][nt][3] + b1);
            *(float2*)(C + (size_t)r * 256 + cl)       = v0;
            *(float2*)(C + (size_t)(r + 8) * 256 + cl) = v1;
        }
    }
}

// ---------------------------------------------------------------------------
// Sampler (passing R10 version): fused g_qproj, fp16 g_v16 gathers.
// ---------------------------------------------------------------------------
__global__ __launch_bounds__(256)
void sample_kernel(const float* __restrict__ refwin,
                   float* __restrict__ awout)
{
    __shared__ float  sh_raw[128];
    __shared__ float  sh_off[128];
    __shared__ float2 sh_swlw[H_][64];
    __shared__ int4   sh_idx[512];
    __shared__ float4 sh_w[512];

    const int bq   = blockIdx.x;
    const int b    = bq >> 10;
    const int t    = threadIdx.x;
    const int h    = t >> 5;
    const int lane = t & 31;

    if (t < 128) sh_off[t] = g_qproj[(size_t)bq * 256 + t];
    else         sh_raw[t - 128] = g_qproj[(size_t)bq * 256 + t];
    __syncthreads();

    float e[2];
    int   aidx[2];
#pragma unroll
    for (int tgt = 0; tgt < 2; tgt++) {
        int n = lane + 32 * tgt;
        int l = n >> 4, kk = n & 15, ii = kk >> 2, jj = kk & 3;
        int a = ((ii >> 1) << 1) + (jj >> 1);
        aidx[tgt] = a;
        e[tgt] = sh_raw[h * 16 + l * 4 + a];
    }
    awout[(size_t)bq * 512 + h * 64 + lane]      = e[0];
    awout[(size_t)bq * 512 + h * 64 + lane + 32] = e[1];

    float m = fmaxf(e[0], e[1]);
#pragma unroll
    for (int o = 16; o > 0; o >>= 1) m = fmaxf(m, __shfl_xor_sync(0xffffffffu, m, o));
    float p0 = __expf(e[0] - m), p1 = __expf(e[1] - m);
    float s = p0 + p1;
#pragma unroll
    for (int o = 16; o > 0; o >>= 1) s += __shfl_xor_sync(0xffffffffu, s, o);
    float inv = 1.f / s;

#pragma unroll
    for (int tgt = 0; tgt < 2; tgt++) {
        int a = aidx[tgt];
        float r0 = sh_raw[h * 16 + 0 + a], r1 = sh_raw[h * 16 + 4 + a];
        float r2 = sh_raw[h * 16 + 8 + a], r3 = sh_raw[h * 16 + 12 + a];
        float m4 = fmaxf(fmaxf(r0, r1), fmaxf(r2, r3));
        float s4 = __expf(r0 - m4) + __expf(r1 - m4) + __expf(r2 - m4) + __expf(r3 - m4);
        float lw = __expf(e[tgt] - m4) / s4;
        float sw = (tgt == 0 ? p0 : p1) * inv;
        sh_swlw[h][lane + 32 * tgt] = make_float2(sw, lw);
    }

    const float rcx = refwin[bq * 4 + 0];
    const float rcy = refwin[bq * 4 + 1];
    const float rsx = refwin[bq * 4 + 2];
    const float rsy = refwin[bq * 4 + 3];

#pragma unroll
    for (int rep = 0; rep < 2; rep++) {
        int sidx = t + rep * 256;
        int hh = sidx >> 6;
        int n  = sidx & 63;
        int l  = n >> 4;
        int ii = (n >> 2) & 3;
        int jj = n & 3;

        float o0 = sh_off[hh * 16 + l * 4 + 0];
        float o1 = sh_off[hh * 16 + l * 4 + 1];
        float o2 = sh_off[hh * 16 + l * 4 + 2];
        float o3 = sh_off[hh * 16 + l * 4 + 3];
        float cx = rcx + o0 * 0.125f * rsx;
        float cy = rcy + o1 * 0.125f * rsy;
        float sx = fmaxf(rsx + o2 * 0.125f * rsx, 0.f);
        float sy = fmaxf(rsy + o3 * 0.125f * rsy, 0.f);

        int   Wl  = 128 >> l;
        float fW  = (float)Wl;
        int base  = (l == 0) ? 0 : (l == 1) ? 16384 : (l == 2) ? 20480 : 21504;

        float y   = (cy + ((float)ii - 1.5f) * 0.25f * sy) * fW - 0.5f;
        float x   = (cx + ((float)jj - 1.5f) * 0.25f * sx) * fW - 0.5f;
        float y0f = floorf(y);
        float x0f = floorf(x);
        float fy  = y - y0f;
        float fx  = x - x0f;
        int y0 = (int)y0f;
        int x0 = (int)x0f;
        bool vy0 = (y0 >= 0) && (y0 < Wl);
        bool vy1 = (y0 >= -1) && (y0 < Wl - 1);
        bool vx0 = (x0 >= 0) && (x0 < Wl);
        bool vx1 = (x0 >= -1) && (x0 < Wl - 1);
        int cy0 = min(max(y0, 0), Wl - 1);
        int cy1 = min(max(y0 + 1, 0), Wl - 1);
        int cx0 = min(max(x0, 0), Wl - 1);
        int cx1 = min(max(x0 + 1, 0), Wl - 1);

        int4 id;
        id.x = (base + cy0 * Wl + cx0) * 256;
        id.y = (base + cy0 * Wl + cx1) * 256;
        id.z = (base + cy1 * Wl + cx0) * 256;
        id.w = (base + cy1 * Wl + cx1) * 256;
        float4 w;
        w.x = (vx0 && vy0) ? (1.f - fx) * (1.f - fy) : 0.f;
        w.y = (vx1 && vy0) ? fx * (1.f - fy) : 0.f;
        w.z = (vx0 && vy1) ? (1.f - fx) * fy : 0.f;
        w.w = (vx1 && vy1) ? fx * fy : 0.f;
        sh_idx[sidx] = id;
        sh_w[sidx]   = w;
    }
    __syncthreads();

    const __half* vb = g_v16 + (size_t)b * L2_ * 256 + h * 32 + lane;
    float acc_o = 0.f, acc_m = 0.f;

#pragma unroll 8
    for (int n = 0; n < 64; n++) {
        int4   id = sh_idx[h * 64 + n];
        float4 w  = sh_w[h * 64 + n];
        float val = w.x * __half2float(vb[id.x]) + w.y * __half2float(vb[id.y])
                  + w.z * __half2float(vb[id.z]) + w.w * __half2float(vb[id.w]);
        float2 sl = sh_swlw[h][n];
        acc_o += sl.x * val;
        acc_m += sl.y * val;
    }

    const size_t od = (size_t)bq * D_ + h * HD_ + lane;
    g_outpre[od]  = acc_o;
    g_moutpre[od] = acc_m;
}

// ---------------------------------------------------------------------------
extern "C" void kernel_launch(void* const* d_in, const int* in_sizes, int n_in,
                              void* d_out, int out_size)
{
    const float* query = (const float*)d_in[0];
    const float* value = (const float*)d_in[1];
    const float* refw  = (const float*)d_in[2];
    const float* Wv    = (const float*)d_in[3];
    const float* bv    = (const float*)d_in[4];
    const float* Wo    = (const float*)d_in[5];
    const float* bo    = (const float*)d_in[6];
    const float* Wbox  = (const float*)d_in[7];
    const float* bbox  = (const float*)d_in[8];
    const float* Wattn = (const float*)d_in[9];
    const float* battn = (const float*)d_in[10];
    const unsigned char* vmask = (const unsigned char*)d_in[13];

    float* out   = (float*)d_out;
    float* mout  = out  + (size_t)NQ_ * D_;
    float* awout = mout + (size_t)NQ_ * D_;

    float *pqp, *pop, *pmp, *pbq;
    __half *pval16, *pv16, *pwvh, *pwoh, *pwol, *pwqh, *pwql;
    cudaGetSymbolAddress((void**)&pval16, g_val16);
    cudaGetSymbolAddress((void**)&pv16,   g_v16);
    cudaGetSymbolAddress((void**)&pqp,    g_qproj);
    cudaGetSymbolAddress((void**)&pop,    g_outpre);
    cudaGetSymbolAddress((void**)&pmp,    g_moutpre);
    cudaGetSymbolAddress((void**)&pwvh,   g_Wvh);
    cudaGetSymbolAddress((void**)&pwoh,   g_Woh);
    cudaGetSymbolAddress((void**)&pwol,   g_Wol);
    cudaGetSymbolAddress((void**)&pwqh,   g_Wqh);
    cudaGetSymbolAddress((void**)&pwql,   g_Wql);
    cudaGetSymbolAddress((void**)&pbq,    g_bq);

    const int VSMEM = VA_SZ + 4 * VW_STG + 1024;   // 132096
    cudaFuncSetAttribute(hmma_gemm_v,
                         cudaFuncAttributeMaxDynamicSharedMemorySize, VSMEM);

    // 0) prep: weights; value -> fp16
    prep_w_kernel<<<256, 256>>>(Wv, Wo, Wbox, Wattn, bbox, battn);
    prep_v_kernel<<<MV_ * D_ / 4 / 256, 256>>>(value);
    // 1) fused q projection
    hmma_gemm_fp16<<<dim3(NQ_ / 128, 1), 512>>>(query, query, pwqh, pwql, pbq,
                                                pqp, pqp);
    // 2) v = value @ Wv^T + bv (fp16 out, masked; A-resident W-streamed)
    hmma_gemm_v<<<MV_ / 128, 512, VSMEM>>>(pval16, pwvh, bv, pv16, vmask);
    // 3) softmaxes + sampling
    sample_kernel<<<NQ_, 256>>>(refw, awout);
    // 4) out + mout projections (fused, one launch)
    hmma_gemm_fp16<<<dim3(NQ_ / 128, 2), 512>>>(pop, pmp, pwoh, pwol, bo,
                                                out, mout);
}

// round 13
// speedup vs baseline: 1.7201x; 1.0652x over previous
#include <cuda_runtime.h>
#include <cuda_fp16.h>
#include <cstdint>
#include <cstring>

#define B_   4
#define L1_  1024
#define D_   256
#define H_   8
#define HD_  32
#define L_   4
#define L2_  21760
#define NQ_  (B_ * L1_)          // 4096
#define MV_  (B_ * L2_)          // 87040

// ---------------- scratch (static device memory; no allocs) ----------------
__device__ __half g_v16[(size_t)MV_ * D_];      // fp16 v = value @ Wv^T (44.5 MB)
__device__ float  g_qproj[(size_t)NQ_ * 256];   // [off | aw] fused projection
__device__ float  g_outpre[(size_t)NQ_ * D_];
__device__ float  g_moutpre[(size_t)NQ_ * D_];
__device__ __half g_Wvh[65536];                 // Wv fp16 (single pass)
__device__ __half g_Woh[65536], g_Wol[65536];   // Wo fp16 hi/lo
__device__ __half g_Wqh[65536], g_Wql[65536];   // [Wbox;Wattn] fp16 hi/lo
__device__ float  g_bq[256];                    // [bbox | battn]

// ===========================================================================
// helpers
// ===========================================================================
__device__ __forceinline__ uint32_t h2_bits(__half2 h) {
    uint32_t u;
    memcpy(&u, &h, 4);
    return u;
}
__device__ __forceinline__ uint32_t smem_u32(const void* p) {
    uint32_t a;
    asm("{ .reg .u64 t; cvta.to.shared.u64 t, %1; cvt.u32.u64 %0, t; }"
        : "=r"(a) : "l"(p));
    return a;
}
__device__ __forceinline__ void ldmx4(uint32_t addr, uint32_t& r0, uint32_t& r1,
                                      uint32_t& r2, uint32_t& r3) {
    asm volatile("ldmatrix.sync.aligned.m8n8.x4.shared.b16 {%0,%1,%2,%3}, [%4];"
                 : "=r"(r0), "=r"(r1), "=r"(r2), "=r"(r3) : "r"(addr));
}
__device__ __forceinline__ void mma16816(float* d, const uint32_t* a,
                                         const uint32_t* b) {
    asm volatile("mma.sync.aligned.m16n8k16.row.col.f32.f16.f16.f32 "
                 "{%0,%1,%2,%3}, {%4,%5,%6,%7}, {%8,%9}, {%0,%1,%2,%3};"
                 : "+f"(d[0]), "+f"(d[1]), "+f"(d[2]), "+f"(d[3])
                 : "r"(a[0]), "r"(a[1]), "r"(a[2]), "r"(a[3]),
                   "r"(b[0]), "r"(b[1]));
}
#define CP_ASYNC16(dst, src) \
    asm volatile("cp.async.cg.shared.global [%0], [%1], 16;" :: "r"(dst), "l"(src))
#define CP_COMMIT() asm volatile("cp.async.commit_group;" ::: "memory")
#define CP_WAIT0()  asm volatile("cp.async.wait_group 0;" ::: "memory")

// ---------------------------------------------------------------------------
// prep: weights -> fp16 (Wv single, Wo/[Wbox;Wattn] hi/lo); bias pack
// ---------------------------------------------------------------------------
__global__ void prep_w_kernel(const float* __restrict__ Wv,
                              const float* __restrict__ Wo,
                              const float* __restrict__ Wbox,
                              const float* __restrict__ Wattn,
                              const float* __restrict__ bbox,
                              const float* __restrict__ battn)
{
    int i = blockIdx.x * blockDim.x + threadIdx.x;   // 0..65535
    g_Wvh[i] = __float2half_rn(Wv[i]);
    float o = Wo[i];
    __half ho = __float2half_rn(o);
    g_Woh[i] = ho;
    g_Wol[i] = __float2half_rn(o - __half2float(ho));
    int r = i >> 8, c = i & 255;
    float q = (r < 128) ? Wbox[r * 256 + c] : Wattn[(r - 128) * 256 + c];
    __half hq = __float2half_rn(q);
    g_Wqh[i] = hq;
    g_Wql[i] = __float2half_rn(q - __half2float(hq));
    if (i < 256) g_bq[i] = (i < 128) ? bbox[i] : battn[i - 128];
}

// ===========================================================================
// Value GEMM: C16[M,256] = fp16(A[M,256]) @ Wh^T + b, masked rows zeroed.
// W (256x256 fp16 = 128KB) fully smem-resident (one cp.async prologue);
// A loaded fp32 chunk-by-chunk, converted to fp16 in-register, STS into a
// 2x8KB double buffer (prefetch distance 1). 512 thr, warp tile 32x64.
// smem layout: [0,128K) W chunks (8 x 16KB); [128K,144K) A bufs; bias after.
// total = 131072 + 16384 + 1024 = 148480 B
// ===========================================================================
#define VW_SZ   131072
#define VA_BUF  8192
__global__ __launch_bounds__(512)
void hmma_gemm_v(const float* __restrict__ A,
                 const __half* __restrict__ Wh,
                 const float* __restrict__ bias,
                 __half* __restrict__ C,
                 const unsigned char* __restrict__ mask)
{
    extern __shared__ __align__(16) unsigned char dsm[];
    float* bias_s = (float*)(dsm + VW_SZ + 2 * VA_BUF);

    const int t    = threadIdx.x;
    const int wid  = t >> 5;
    const int lane = t & 31;
    const int wm   = wid & 3;
    const int wn   = wid >> 2;
    const int m0   = blockIdx.x * 128;
    const uint32_t base  = smem_u32(dsm);
    const uint32_t abase = base + VW_SZ;

    if (t < 256) bias_s[t] = bias[t];

    float acc[2][8][4];
#pragma unroll
    for (int mt = 0; mt < 2; mt++)
#pragma unroll
        for (int nt = 0; nt < 8; nt++)
#pragma unroll
            for (int i = 0; i < 4; i++) acc[mt][nt][i] = 0.f;

    // ---- prologue: full W (128KB) via cp.async; A chunk 0 via LDG ----
#pragma unroll
    for (int u = 0; u < 16; u++) {
        int f  = t + u * 512;     // 0..8191 16B units
        int r  = f >> 5;          // 0..255
        int j  = f & 31;          // unit within 512B row
        int ch = j >> 2;
        int cu = j & 3;
        uint32_t dst = base + ch * 16384 + r * 64 + ((cu ^ ((r >> 1) & 3)) * 16);
        CP_ASYNC16(dst, Wh + (size_t)r * 256 + j * 8);
    }
    CP_COMMIT();

    const int ar = t >> 2;        // A row 0..127
    const int au = t & 3;         // 16B unit within 64B chunk-row
    const uint32_t asw = ((au ^ ((ar >> 1) & 3)) * 16) + ar * 64;
    const float* asrc = A + (size_t)(m0 + ar) * 256 + au * 8;

    float4 pa0 = *(const float4*)(asrc);
    float4 pa1 = *(const float4*)(asrc + 4);

    CP_WAIT0();                   // W resident
    {
        uint4 u;
        u.x = h2_bits(__floats2half2_rn(pa0.x, pa0.y));
        u.y = h2_bits(__floats2half2_rn(pa0.z, pa0.w));
        u.z = h2_bits(__floats2half2_rn(pa1.x, pa1.y));
        u.w = h2_bits(__floats2half2_rn(pa1.z, pa1.w));
        *(uint4*)(dsm + VW_SZ + asw) = u;
    }
    __syncthreads();

    for (int ch = 0; ch < 8; ch++) {
        // prefetch next A chunk (fp32) into registers
        if (ch < 7) {
            pa0 = *(const float4*)(asrc + (ch + 1) * 32);
            pa1 = *(const float4*)(asrc + (ch + 1) * 32 + 4);
        }

        const uint32_t uA = abase + (ch & 1) * VA_BUF;
        const uint32_t uB = base + ch * 16384;

#pragma unroll
        for (int s = 0; s < 2; s++) {
            uint32_t ah[2][4];
#pragma unroll
            for (int mt = 0; mt < 2; mt++) {
                int row  = wm * 32 + mt * 16 + (lane & 15);
                int unit = s * 2 + (lane >> 4);
                ldmx4(uA + row * 64 + (unit ^ ((row >> 1) & 3)) * 16,
                      ah[mt][0], ah[mt][1], ah[mt][2], ah[mt][3]);
            }
#pragma unroll
            for (int half = 0; half < 2; half++) {
                uint32_t bh[4][2];
#pragma unroll
                for (int p = 0; p < 2; p++) {
                    int pp   = half * 2 + p;
                    int nrow = wn * 64 + pp * 16 + (lane & 7) + (((lane >> 4) & 1) << 3);
                    int unit = s * 2 + ((lane >> 3) & 1);
                    uint32_t off = nrow * 64 + (unit ^ ((nrow >> 1) & 3)) * 16;
                    ldmx4(uB + off, bh[p*2][0], bh[p*2][1], bh[p*2+1][0], bh[p*2+1][1]);
                }
#pragma unroll
                for (int mt = 0; mt < 2; mt++)
#pragma unroll
                    for (int q = 0; q < 4; q++)
                        mma16816(acc[mt][half * 4 + q], ah[mt], bh[q]);
            }
        }

        // convert + store next A chunk, then barrier
        if (ch < 7) {
            uint4 u;
            u.x = h2_bits(__floats2half2_rn(pa0.x, pa0.y));
            u.y = h2_bits(__floats2half2_rn(pa0.z, pa0.w));
            u.z = h2_bits(__floats2half2_rn(pa1.x, pa1.y));
            u.w = h2_bits(__floats2half2_rn(pa1.z, pa1.w));
            *(uint4*)(dsm + VW_SZ + ((ch + 1) & 1) * VA_BUF + asw) = u;
            __syncthreads();
        }
    }

    // epilogue: bias + mask, fp16 stores
    const int rw = lane >> 2;
    const int cw = (lane & 3) * 2;
#pragma unroll
    for (int mt = 0; mt < 2; mt++) {
        int r = m0 + wm * 32 + mt * 16 + rw;
        bool z0 = mask[r] != 0;
        bool z1 = mask[r + 8] != 0;
#pragma unroll
        for (int nt = 0; nt < 8; nt++) {
            int cl = wn * 64 + nt * 8 + cw;
            float b0 = bias_s[cl], b1 = bias_s[cl + 1];
            __half2 v0 = __floats2half2_rn(z0 ? 0.f : acc[mt][nt][0] + b0,
                                           z0 ? 0.f : acc[mt][nt][1] + b1);
            __half2 v1 = __floats2half2_rn(z1 ? 0.f : acc[mt][nt][2] + b0,
                                           z1 ? 0.f : acc[mt][nt][3] + b1);
            *(__half2*)(C + (size_t)r * 256 + cl)       = v0;
            *(__half2*)(C + (size_t)(r + 8) * 256 + cl) = v1;
        }
    }
}

// ===========================================================================
// fp32-A 2-pass HMMA GEMM (q-projection, out/mout): C[M,256] fp32.
// blockIdx.y selects (A0,C0) or (A1,C1).
// ===========================================================================
__global__ __launch_bounds__(512)
void hmma_gemm_fp16(const float* __restrict__ A0,
                    const float* __restrict__ A1,
                    const __half* __restrict__ Wh,
                    const __half* __restrict__ Wl,
                    const float* __restrict__ bias,
                    float* __restrict__ C0,
                    float* __restrict__ C1)
{
    __shared__ __align__(16) unsigned char smA [128 * 64];
    __shared__ __align__(16) unsigned char smBh[256 * 64];
    __shared__ __align__(16) unsigned char smBl[256 * 64];
    __shared__ float bias_s[256];

    const float* A = blockIdx.y ? A1 : A0;
    float*       C = blockIdx.y ? C1 : C0;

    const int t    = threadIdx.x;
    const int wid  = t >> 5;
    const int lane = t & 31;
    const int wm   = wid & 3;
    const int wn   = wid >> 2;
    const int m0   = blockIdx.x * 128;

    if (t < 256) bias_s[t] = bias[t];

    float acc[2][8][4];
#pragma unroll
    for (int mt = 0; mt < 2; mt++)
#pragma unroll
        for (int nt = 0; nt < 8; nt++)
#pragma unroll
            for (int i = 0; i < 4; i++) acc[mt][nt][i] = 0.f;

    const uint32_t uA  = smem_u32(smA);
    const uint32_t uBh = smem_u32(smBh);
    const uint32_t uBl = smem_u32(smBl);

    for (int k0 = 0; k0 < 256; k0 += 32) {
        {
            int r  = t >> 2;
            int c4 = t & 3;
            const float* src = A + (size_t)(m0 + r) * 256 + k0 + c4 * 8;
            float4 v0 = *(const float4*)(src);
            float4 v1 = *(const float4*)(src + 4);
            uint4 u;
            u.x = h2_bits(__floats2half2_rn(v0.x, v0.y));
            u.y = h2_bits(__floats2half2_rn(v0.z, v0.w));
            u.z = h2_bits(__floats2half2_rn(v1.x, v1.y));
            u.w = h2_bits(__floats2half2_rn(v1.z, v1.w));
            *(uint4*)(smA + r * 64 + (c4 ^ ((r >> 1) & 3)) * 16) = u;
        }
#pragma unroll
        for (int u = 0; u < 2; u++) {
            int f   = t + u * 512;
            int r   = f >> 2;
            int c16 = f & 3;
            uint32_t dst = r * 64 + (c16 ^ ((r >> 1) & 3)) * 16;
            *(uint4*)(smBh + dst) = *(const uint4*)(Wh + (size_t)r * 256 + k0 + c16 * 8);
            *(uint4*)(smBl + dst) = *(const uint4*)(Wl + (size_t)r * 256 + k0 + c16 * 8);
        }
        __syncthreads();

#pragma unroll
        for (int s = 0; s < 2; s++) {
            uint32_t ah[2][4];
#pragma unroll
            for (int mt = 0; mt < 2; mt++) {
                int row  = wm * 32 + mt * 16 + (lane & 15);
                int unit = s * 2 + (lane >> 4);
                ldmx4(uA + row * 64 + (unit ^ ((row >> 1) & 3)) * 16,
                      ah[mt][0], ah[mt][1], ah[mt][2], ah[mt][3]);
            }
#pragma unroll
            for (int half = 0; half < 2; half++) {
                uint32_t bh[4][2], bl[4][2];
#pragma unroll
                for (int p = 0; p < 2; p++) {
                    int pp   = half * 2 + p;
                    int nrow = wn * 64 + pp * 16 + (lane & 7) + (((lane >> 4) & 1) << 3);
                    int unit = s * 2 + ((lane >> 3) & 1);
                    uint32_t off = nrow * 64 + (unit ^ ((nrow >> 1) & 3)) * 16;
                    ldmx4(uBh + off, bh[p*2][0], bh[p*2][1], bh[p*2+1][0], bh[p*2+1][1]);
                    ldmx4(uBl + off, bl[p*2][0], bl[p*2][1], bl[p*2+1][0], bl[p*2+1][1]);
                }
#pragma unroll
                for (int mt = 0; mt < 2; mt++)
#pragma unroll
                    for (int q = 0; q < 4; q++) {
                        int nt = half * 4 + q;
                        mma16816(acc[mt][nt], ah[mt], bh[q]);
                        mma16816(acc[mt][nt], ah[mt], bl[q]);
                    }
            }
        }
        __syncthreads();
    }

    const int rw = lane >> 2;
    const int cw = (lane & 3) * 2;
#pragma unroll
    for (int mt = 0; mt < 2; mt++) {
        int r = m0 + wm * 32 + mt * 16 + rw;
#pragma unroll
        for (int nt = 0; nt < 8; nt++) {
            int cl = wn * 64 + nt * 8 + cw;
            float b0 = bias_s[cl], b1 = bias_s[cl + 1];
            float2 v0 = make_float2(acc[mt][nt][0] + b0, acc[mt][nt][1] + b1);
            float2 v1 = make_float2(acc[mt][nt][2] + b0, acc[mt][nt][3] + b1);
            *(float2*)(C + (size_t)r * 256 + cl)       = v0;
            *(float2*)(C + (size_t)(r + 8) * 256 + cl) = v1;
        }
    }
}

// ---------------------------------------------------------------------------
// Sampler (passing R12 version): fused g_qproj, fp16 g_v16 gathers.
// ---------------------------------------------------------------------------
__global__ __launch_bounds__(256)
void sample_kernel(const float* __restrict__ refwin,
                   float* __restrict__ awout)
{
    __shared__ float  sh_raw[128];
    __shared__ float  sh_off[128];
    __shared__ float2 sh_swlw[H_][64];
    __shared__ int4   sh_idx[512];
    __shared__ float4 sh_w[512];

    const int bq   = blockIdx.x;
    const int b    = bq >> 10;
    const int t    = threadIdx.x;
    const int h    = t >> 5;
    const int lane = t & 31;

    if (t < 128) sh_off[t] = g_qproj[(size_t)bq * 256 + t];
    else         sh_raw[t - 128] = g_qproj[(size_t)bq * 256 + t];
    __syncthreads();

    float e[2];
    int   aidx[2];
#pragma unroll
    for (int tgt = 0; tgt < 2; tgt++) {
        int n = lane + 32 * tgt;
        int l = n >> 4, kk = n & 15, ii = kk >> 2, jj = kk & 3;
        int a = ((ii >> 1) << 1) + (jj >> 1);
        aidx[tgt] = a;
        e[tgt] = sh_raw[h * 16 + l * 4 + a];
    }
    awout[(size_t)bq * 512 + h * 64 + lane]      = e[0];
    awout[(size_t)bq * 512 + h * 64 + lane + 32] = e[1];

    float m = fmaxf(e[0], e[1]);
#pragma unroll
    for (int o = 16; o > 0; o >>= 1) m = fmaxf(m, __shfl_xor_sync(0xffffffffu, m, o));
    float p0 = __expf(e[0] - m), p1 = __expf(e[1] - m);
    float s = p0 + p1;
#pragma unroll
    for (int o = 16; o > 0; o >>= 1) s += __shfl_xor_sync(0xffffffffu, s, o);
    float inv = 1.f / s;

#pragma unroll
    for (int tgt = 0; tgt < 2; tgt++) {
        int a = aidx[tgt];
        float r0 = sh_raw[h * 16 + 0 + a], r1 = sh_raw[h * 16 + 4 + a];
        float r2 = sh_raw[h * 16 + 8 + a], r3 = sh_raw[h * 16 + 12 + a];
        float m4 = fmaxf(fmaxf(r0, r1), fmaxf(r2, r3));
        float s4 = __expf(r0 - m4) + __expf(r1 - m4) + __expf(r2 - m4) + __expf(r3 - m4);
        float lw = __expf(e[tgt] - m4) / s4;
        float sw = (tgt == 0 ? p0 : p1) * inv;
        sh_swlw[h][lane + 32 * tgt] = make_float2(sw, lw);
    }

    const float rcx = refwin[bq * 4 + 0];
    const float rcy = refwin[bq * 4 + 1];
    const float rsx = refwin[bq * 4 + 2];
    const float rsy = refwin[bq * 4 + 3];

#pragma unroll
    for (int rep = 0; rep < 2; rep++) {
        int sidx = t + rep * 256;
        int hh = sidx >> 6;
        int n  = sidx & 63;
        int l  = n >> 4;
        int ii = (n >> 2) & 3;
        int jj = n & 3;

        float o0 = sh_off[hh * 16 + l * 4 + 0];
        float o1 = sh_off[hh * 16 + l * 4 + 1];
        float o2 = sh_off[hh * 16 + l * 4 + 2];
        float o3 = sh_off[hh * 16 + l * 4 + 3];
        float cx = rcx + o0 * 0.125f * rsx;
        float cy = rcy + o1 * 0.125f * rsy;
        float sx = fmaxf(rsx + o2 * 0.125f * rsx, 0.f);
        float sy = fmaxf(rsy + o3 * 0.125f * rsy, 0.f);

        int   Wl  = 128 >> l;
        float fW  = (float)Wl;
        int base  = (l == 0) ? 0 : (l == 1) ? 16384 : (l == 2) ? 20480 : 21504;

        float y   = (cy + ((float)ii - 1.5f) * 0.25f * sy) * fW - 0.5f;
        float x   = (cx + ((float)jj - 1.5f) * 0.25f * sx) * fW - 0.5f;
        float y0f = floorf(y);
        float x0f = floorf(x);
        float fy  = y - y0f;
        float fx  = x - x0f;
        int y0 = (int)y0f;
        int x0 = (int)x0f;
        bool vy0 = (y0 >= 0) && (y0 < Wl);
        bool vy1 = (y0 >= -1) && (y0 < Wl - 1);
        bool vx0 = (x0 >= 0) && (x0 < Wl);
        bool vx1 = (x0 >= -1) && (x0 < Wl - 1);
        int cy0 = min(max(y0, 0), Wl - 1);
        int cy1 = min(max(y0 + 1, 0), Wl - 1);
        int cx0 = min(max(x0, 0), Wl - 1);
        int cx1 = min(max(x0 + 1, 0), Wl - 1);

        int4 id;
        id.x = (base + cy0 * Wl + cx0) * 256;
        id.y = (base + cy0 * Wl + cx1) * 256;
        id.z = (base + cy1 * Wl + cx0) * 256;
        id.w = (base + cy1 * Wl + cx1) * 256;
        float4 w;
        w.x = (vx0 && vy0) ? (1.f - fx) * (1.f - fy) : 0.f;
        w.y = (vx1 && vy0) ? fx * (1.f - fy) : 0.f;
        w.z = (vx0 && vy1) ? (1.f - fx) * fy : 0.f;
        w.w = (vx1 && vy1) ? fx * fy : 0.f;
        sh_idx[sidx] = id;
        sh_w[sidx]   = w;
    }
    __syncthreads();

    const __half* vb = g_v16 + (size_t)b * L2_ * 256 + h * 32 + lane;
    float acc_o = 0.f, acc_m = 0.f;

#pragma unroll 8
    for (int n = 0; n < 64; n++) {
        int4   id = sh_idx[h * 64 + n];
        float4 w  = sh_w[h * 64 + n];
        float val = w.x * __half2float(vb[id.x]) + w.y * __half2float(vb[id.y])
                  + w.z * __half2float(vb[id.z]) + w.w * __half2float(vb[id.w]);
        float2 sl = sh_swlw[h][n];
        acc_o += sl.x * val;
        acc_m += sl.y * val;
    }

    const size_t od = (size_t)bq * D_ + h * HD_ + lane;
    g_outpre[od]  = acc_o;
    g_moutpre[od] = acc_m;
}

// ---------------------------------------------------------------------------
extern "C" void kernel_launch(void* const* d_in, const int* in_sizes, int n_in,
                              void* d_out, int out_size)
{
    const float* query = (const float*)d_in[0];
    const float* value = (const float*)d_in[1];
    const float* refw  = (const float*)d_in[2];
    const float* Wv    = (const float*)d_in[3];
    const float* bv    = (const float*)d_in[4];
    const float* Wo    = (const float*)d_in[5];
    const float* bo    = (const float*)d_in[6];
    const float* Wbox  = (const float*)d_in[7];
    const float* bbox  = (const float*)d_in[8];
    const float* Wattn = (const float*)d_in[9];
    const float* battn = (const float*)d_in[10];
    const unsigned char* vmask = (const unsigned char*)d_in[13];

    float* out   = (float*)d_out;
    float* mout  = out  + (size_t)NQ_ * D_;
    float* awout = mout + (size_t)NQ_ * D_;

    float *pqp, *pop, *pmp, *pbq;
    __half *pv16, *pwvh, *pwoh, *pwol, *pwqh, *pwql;
    cudaGetSymbolAddress((void**)&pv16,   g_v16);
    cudaGetSymbolAddress((void**)&pqp,    g_qproj);
    cudaGetSymbolAddress((void**)&pop,    g_outpre);
    cudaGetSymbolAddress((void**)&pmp,    g_moutpre);
    cudaGetSymbolAddress((void**)&pwvh,   g_Wvh);
    cudaGetSymbolAddress((void**)&pwoh,   g_Woh);
    cudaGetSymbolAddress((void**)&pwol,   g_Wol);
    cudaGetSymbolAddress((void**)&pwqh,   g_Wqh);
    cudaGetSymbolAddress((void**)&pwql,   g_Wql);
    cudaGetSymbolAddress((void**)&pbq,    g_bq);

    const int VSMEM = VW_SZ + 2 * VA_BUF + 1024;   // 148480
    cudaFuncSetAttribute(hmma_gemm_v,
                         cudaFuncAttributeMaxDynamicSharedMemorySize, VSMEM);

    // 0) prep: weights -> fp16
    prep_w_kernel<<<256, 256>>>(Wv, Wo, Wbox, Wattn, bbox, battn);
    // 1) fused q projection
    hmma_gemm_fp16<<<dim3(NQ_ / 128, 1), 512>>>(query, query, pwqh, pwql, pbq,
                                                pqp, pqp);
    // 2) v = value @ Wv^T + bv (fp16 out, masked; W-resident, fused convert)
    hmma_gemm_v<<<MV_ / 128, 512, VSMEM>>>(value, pwvh, bv, pv16, vmask);
    // 3) softmaxes + sampling
    sample_kernel<<<NQ_, 256>>>(refw, awout);
    // 4) out + mout projections (fused, one launch)
    hmma_gemm_fp16<<<dim3(NQ_ / 128, 2), 512>>>(pop, pmp, pwoh, pwol, bo,
                                                out, mout);
}

// round 14
// speedup vs baseline: 1.9389x; 1.1272x over previous
#include <cuda_runtime.h>
#include <cuda_fp16.h>
#include <cstdint>
#include <cstring>

#define B_   4
#define L1_  1024
#define D_   256
#define H_   8
#define HD_  32
#define L_   4
#define L2_  21760
#define NQ_  (B_ * L1_)          // 4096
#define MV_  (B_ * L2_)          // 87040

// ---------------- scratch (static device memory; no allocs) ----------------
__device__ __half g_v16[(size_t)MV_ * D_];      // fp16 v = value @ Wv^T (44.5 MB)
__device__ float  g_qproj[(size_t)NQ_ * 256];   // [off | aw] fused projection
__device__ float  g_outpre[(size_t)NQ_ * D_];
__device__ float  g_moutpre[(size_t)NQ_ * D_];
__device__ __half g_Wvh[65536];                 // Wv fp16 (single pass)
__device__ __half g_Woh[65536], g_Wol[65536];   // Wo fp16 hi/lo
__device__ __half g_Wqh[65536], g_Wql[65536];   // [Wbox;Wattn] fp16 hi/lo
__device__ float  g_bq[256];                    // [bbox | battn]

// ===========================================================================
// helpers
// ===========================================================================
__device__ __forceinline__ uint32_t h2_bits(__half2 h) {
    uint32_t u;
    memcpy(&u, &h, 4);
    return u;
}
__device__ __forceinline__ uint32_t smem_u32(const void* p) {
    uint32_t a;
    asm("{ .reg .u64 t; cvta.to.shared.u64 t, %1; cvt.u32.u64 %0, t; }"
        : "=r"(a) : "l"(p));
    return a;
}
__device__ __forceinline__ void ldmx4(uint32_t addr, uint32_t& r0, uint32_t& r1,
                                      uint32_t& r2, uint32_t& r3) {
    asm volatile("ldmatrix.sync.aligned.m8n8.x4.shared.b16 {%0,%1,%2,%3}, [%4];"
                 : "=r"(r0), "=r"(r1), "=r"(r2), "=r"(r3) : "r"(addr));
}
__device__ __forceinline__ void mma16816(float* d, const uint32_t* a,
                                         const uint32_t* b) {
    asm volatile("mma.sync.aligned.m16n8k16.row.col.f32.f16.f16.f32 "
                 "{%0,%1,%2,%3}, {%4,%5,%6,%7}, {%8,%9}, {%0,%1,%2,%3};"
                 : "+f"(d[0]), "+f"(d[1]), "+f"(d[2]), "+f"(d[3])
                 : "r"(a[0]), "r"(a[1]), "r"(a[2]), "r"(a[3]),
                   "r"(b[0]), "r"(b[1]));
}
#define CP_ASYNC16(dst, src) \
    asm volatile("cp.async.cg.shared.global [%0], [%1], 16;" :: "r"(dst), "l"(src))
#define CP_COMMIT() asm volatile("cp.async.commit_group;" ::: "memory")
#define CP_WAIT0()  asm volatile("cp.async.wait_group 0;" ::: "memory")

// ---------------------------------------------------------------------------
// prep: weights -> fp16 (Wv single, Wo/[Wbox;Wattn] hi/lo); bias pack
// ---------------------------------------------------------------------------
__global__ void prep_w_kernel(const float* __restrict__ Wv,
                              const float* __restrict__ Wo,
                              const float* __restrict__ Wbox,
                              const float* __restrict__ Wattn,
                              const float* __restrict__ bbox,
                              const float* __restrict__ battn)
{
    int i = blockIdx.x * blockDim.x + threadIdx.x;   // 0..65535
    g_Wvh[i] = __float2half_rn(Wv[i]);
    float o = Wo[i];
    __half ho = __float2half_rn(o);
    g_Woh[i] = ho;
    g_Wol[i] = __float2half_rn(o - __half2float(ho));
    int r = i >> 8, c = i & 255;
    float q = (r < 128) ? Wbox[r * 256 + c] : Wattn[(r - 128) * 256 + c];
    __half hq = __float2half_rn(q);
    g_Wqh[i] = hq;
    g_Wql[i] = __float2half_rn(q - __half2float(hq));
    if (i < 256) g_bq[i] = (i < 128) ? bbox[i] : battn[i - 128];
}

// ===========================================================================
// Value GEMM (passing R13 version): W smem-resident, fused fp32->fp16 A.
// ===========================================================================
#define VW_SZ   131072
#define VA_BUF  8192
__global__ __launch_bounds__(512)
void hmma_gemm_v(const float* __restrict__ A,
                 const __half* __restrict__ Wh,
                 const float* __restrict__ bias,
                 __half* __restrict__ C,
                 const unsigned char* __restrict__ mask)
{
    extern __shared__ __align__(16) unsigned char dsm[];
    float* bias_s = (float*)(dsm + VW_SZ + 2 * VA_BUF);

    const int t    = threadIdx.x;
    const int wid  = t >> 5;
    const int lane = t & 31;
    const int wm   = wid & 3;
    const int wn   = wid >> 2;
    const int m0   = blockIdx.x * 128;
    const uint32_t base  = smem_u32(dsm);
    const uint32_t abase = base + VW_SZ;

    if (t < 256) bias_s[t] = bias[t];

    float acc[2][8][4];
#pragma unroll
    for (int mt = 0; mt < 2; mt++)
#pragma unroll
        for (int nt = 0; nt < 8; nt++)
#pragma unroll
            for (int i = 0; i < 4; i++) acc[mt][nt][i] = 0.f;

#pragma unroll
    for (int u = 0; u < 16; u++) {
        int f  = t + u * 512;
        int r  = f >> 5;
        int j  = f & 31;
        int ch = j >> 2;
        int cu = j & 3;
        uint32_t dst = base + ch * 16384 + r * 64 + ((cu ^ ((r >> 1) & 3)) * 16);
        CP_ASYNC16(dst, Wh + (size_t)r * 256 + j * 8);
    }
    CP_COMMIT();

    const int ar = t >> 2;
    const int au = t & 3;
    const uint32_t asw = ((au ^ ((ar >> 1) & 3)) * 16) + ar * 64;
    const float* asrc = A + (size_t)(m0 + ar) * 256 + au * 8;

    float4 pa0 = *(const float4*)(asrc);
    float4 pa1 = *(const float4*)(asrc + 4);

    CP_WAIT0();
    {
        uint4 u;
        u.x = h2_bits(__floats2half2_rn(pa0.x, pa0.y));
        u.y = h2_bits(__floats2half2_rn(pa0.z, pa0.w));
        u.z = h2_bits(__floats2half2_rn(pa1.x, pa1.y));
        u.w = h2_bits(__floats2half2_rn(pa1.z, pa1.w));
        *(uint4*)(dsm + VW_SZ + asw) = u;
    }
    __syncthreads();

    for (int ch = 0; ch < 8; ch++) {
        if (ch < 7) {
            pa0 = *(const float4*)(asrc + (ch + 1) * 32);
            pa1 = *(const float4*)(asrc + (ch + 1) * 32 + 4);
        }

        const uint32_t uA = abase + (ch & 1) * VA_BUF;
        const uint32_t uB = base + ch * 16384;

#pragma unroll
        for (int s = 0; s < 2; s++) {
            uint32_t ah[2][4];
#pragma unroll
            for (int mt = 0; mt < 2; mt++) {
                int row  = wm * 32 + mt * 16 + (lane & 15);
                int unit = s * 2 + (lane >> 4);
                ldmx4(uA + row * 64 + (unit ^ ((row >> 1) & 3)) * 16,
                      ah[mt][0], ah[mt][1], ah[mt][2], ah[mt][3]);
            }
#pragma unroll
            for (int half = 0; half < 2; half++) {
                uint32_t bh[4][2];
#pragma unroll
                for (int p = 0; p < 2; p++) {
                    int pp   = half * 2 + p;
                    int nrow = wn * 64 + pp * 16 + (lane & 7) + (((lane >> 4) & 1) << 3);
                    int unit = s * 2 + ((lane >> 3) & 1);
                    uint32_t off = nrow * 64 + (unit ^ ((nrow >> 1) & 3)) * 16;
                    ldmx4(uB + off, bh[p*2][0], bh[p*2][1], bh[p*2+1][0], bh[p*2+1][1]);
                }
#pragma unroll
                for (int mt = 0; mt < 2; mt++)
#pragma unroll
                    for (int q = 0; q < 4; q++)
                        mma16816(acc[mt][half * 4 + q], ah[mt], bh[q]);
            }
        }

        if (ch < 7) {
            uint4 u;
            u.x = h2_bits(__floats2half2_rn(pa0.x, pa0.y));
            u.y = h2_bits(__floats2half2_rn(pa0.z, pa0.w));
            u.z = h2_bits(__floats2half2_rn(pa1.x, pa1.y));
            u.w = h2_bits(__floats2half2_rn(pa1.z, pa1.w));
            *(uint4*)(dsm + VW_SZ + ((ch + 1) & 1) * VA_BUF + asw) = u;
            __syncthreads();
        }
    }

    const int rw = lane >> 2;
    const int cw = (lane & 3) * 2;
#pragma unroll
    for (int mt = 0; mt < 2; mt++) {
        int r = m0 + wm * 32 + mt * 16 + rw;
        bool z0 = mask[r] != 0;
        bool z1 = mask[r + 8] != 0;
#pragma unroll
        for (int nt = 0; nt < 8; nt++) {
            int cl = wn * 64 + nt * 8 + cw;
            float b0 = bias_s[cl], b1 = bias_s[cl + 1];
            __half2 v0 = __floats2half2_rn(z0 ? 0.f : acc[mt][nt][0] + b0,
                                           z0 ? 0.f : acc[mt][nt][1] + b1);
            __half2 v1 = __floats2half2_rn(z1 ? 0.f : acc[mt][nt][2] + b0,
                                           z1 ? 0.f : acc[mt][nt][3] + b1);
            *(__half2*)(C + (size_t)r * 256 + cl)       = v0;
            *(__half2*)(C + (size_t)(r + 8) * 256 + cl) = v1;
        }
    }
}

// ===========================================================================
// fp32-A 2-pass HMMA GEMM (q-projection, out/mout): C[M,256] fp32.
// ===========================================================================
__global__ __launch_bounds__(512)
void hmma_gemm_fp16(const float* __restrict__ A0,
                    const float* __restrict__ A1,
                    const __half* __restrict__ Wh,
                    const __half* __restrict__ Wl,
                    const float* __restrict__ bias,
                    float* __restrict__ C0,
                    float* __restrict__ C1)
{
    __shared__ __align__(16) unsigned char smA [128 * 64];
    __shared__ __align__(16) unsigned char smBh[256 * 64];
    __shared__ __align__(16) unsigned char smBl[256 * 64];
    __shared__ float bias_s[256];

    const float* A = blockIdx.y ? A1 : A0;
    float*       C = blockIdx.y ? C1 : C0;

    const int t    = threadIdx.x;
    const int wid  = t >> 5;
    const int lane = t & 31;
    const int wm   = wid & 3;
    const int wn   = wid >> 2;
    const int m0   = blockIdx.x * 128;

    if (t < 256) bias_s[t] = bias[t];

    float acc[2][8][4];
#pragma unroll
    for (int mt = 0; mt < 2; mt++)
#pragma unroll
        for (int nt = 0; nt < 8; nt++)
#pragma unroll
            for (int i = 0; i < 4; i++) acc[mt][nt][i] = 0.f;

    const uint32_t uA  = smem_u32(smA);
    const uint32_t uBh = smem_u32(smBh);
    const uint32_t uBl = smem_u32(smBl);

    for (int k0 = 0; k0 < 256; k0 += 32) {
        {
            int r  = t >> 2;
            int c4 = t & 3;
            const float* src = A + (size_t)(m0 + r) * 256 + k0 + c4 * 8;
            float4 v0 = *(const float4*)(src);
            float4 v1 = *(const float4*)(src + 4);
            uint4 u;
            u.x = h2_bits(__floats2half2_rn(v0.x, v0.y));
            u.y = h2_bits(__floats2half2_rn(v0.z, v0.w));
            u.z = h2_bits(__floats2half2_rn(v1.x, v1.y));
            u.w = h2_bits(__floats2half2_rn(v1.z, v1.w));
            *(uint4*)(smA + r * 64 + (c4 ^ ((r >> 1) & 3)) * 16) = u;
        }
#pragma unroll
        for (int u = 0; u < 2; u++) {
            int f   = t + u * 512;
            int r   = f >> 2;
            int c16 = f & 3;
            uint32_t dst = r * 64 + (c16 ^ ((r >> 1) & 3)) * 16;
            *(uint4*)(smBh + dst) = *(const uint4*)(Wh + (size_t)r * 256 + k0 + c16 * 8);
            *(uint4*)(smBl + dst) = *(const uint4*)(Wl + (size_t)r * 256 + k0 + c16 * 8);
        }
        __syncthreads();

#pragma unroll
        for (int s = 0; s < 2; s++) {
            uint32_t ah[2][4];
#pragma unroll
            for (int mt = 0; mt < 2; mt++) {
                int row  = wm * 32 + mt * 16 + (lane & 15);
                int unit = s * 2 + (lane >> 4);
                ldmx4(uA + row * 64 + (unit ^ ((row >> 1) & 3)) * 16,
                      ah[mt][0], ah[mt][1], ah[mt][2], ah[mt][3]);
            }
#pragma unroll
            for (int half = 0; half < 2; half++) {
                uint32_t bh[4][2], bl[4][2];
#pragma unroll
                for (int p = 0; p < 2; p++) {
                    int pp   = half * 2 + p;
                    int nrow = wn * 64 + pp * 16 + (lane & 7) + (((lane >> 4) & 1) << 3);
                    int unit = s * 2 + ((lane >> 3) & 1);
                    uint32_t off = nrow * 64 + (unit ^ ((nrow >> 1) & 3)) * 16;
                    ldmx4(uBh + off, bh[p*2][0], bh[p*2][1], bh[p*2+1][0], bh[p*2+1][1]);
                    ldmx4(uBl + off, bl[p*2][0], bl[p*2][1], bl[p*2+1][0], bl[p*2+1][1]);
                }
#pragma unroll
                for (int mt = 0; mt < 2; mt++)
#pragma unroll
                    for (int q = 0; q < 4; q++) {
                        int nt = half * 4 + q;
                        mma16816(acc[mt][nt], ah[mt], bh[q]);
                        mma16816(acc[mt][nt], ah[mt], bl[q]);
                    }
            }
        }
        __syncthreads();
    }

    const int rw = lane >> 2;
    const int cw = (lane & 3) * 2;
#pragma unroll
    for (int mt = 0; mt < 2; mt++) {
        int r = m0 + wm * 32 + mt * 16 + rw;
#pragma unroll
        for (int nt = 0; nt < 8; nt++) {
            int cl = wn * 64 + nt * 8 + cw;
            float b0 = bias_s[cl], b1 = bias_s[cl + 1];
            float2 v0 = make_float2(acc[mt][nt][0] + b0, acc[mt][nt][1] + b1);
            float2 v1 = make_float2(acc[mt][nt][2] + b0, acc[mt][nt][3] + b1);
            *(float2*)(C + (size_t)r * 256 + cl)       = v0;
            *(float2*)(C + (size_t)(r + 8) * 256 + cl) = v1;
        }
    }
}

// ---------------------------------------------------------------------------
// Sampler v3: half2 gather lanes, 2 samples/iteration.
// lane = (sp = lane>>4) sample parity, (lo = lane&15) half2 channel pair.
// Indices stored in half2 units with head offset baked in.
// ---------------------------------------------------------------------------
__global__ __launch_bounds__(256)
void sample_kernel(const float* __restrict__ refwin,
                   float* __restrict__ awout)
{
    __shared__ float  sh_raw[128];
    __shared__ float  sh_off[128];
    __shared__ float2 sh_swlw[H_][64];
    __shared__ int4   sh_idx[512];
    __shared__ float4 sh_w[512];

    const int bq   = blockIdx.x;
    const int b    = bq >> 10;
    const int t    = threadIdx.x;
    const int h    = t >> 5;
    const int lane = t & 31;

    if (t < 128) sh_off[t] = g_qproj[(size_t)bq * 256 + t];
    else         sh_raw[t - 128] = g_qproj[(size_t)bq * 256 + t];
    __syncthreads();

    // ---- softmaxes (warp = head) ----
    float e[2];
    int   aidx[2];
#pragma unroll
    for (int tgt = 0; tgt < 2; tgt++) {
        int n = lane + 32 * tgt;
        int l = n >> 4, kk = n & 15, ii = kk >> 2, jj = kk & 3;
        int a = ((ii >> 1) << 1) + (jj >> 1);
        aidx[tgt] = a;
        e[tgt] = sh_raw[h * 16 + l * 4 + a];
    }
    awout[(size_t)bq * 512 + h * 64 + lane]      = e[0];
    awout[(size_t)bq * 512 + h * 64 + lane + 32] = e[1];

    float m = fmaxf(e[0], e[1]);
#pragma unroll
    for (int o = 16; o > 0; o >>= 1) m = fmaxf(m, __shfl_xor_sync(0xffffffffu, m, o));
    float p0 = __expf(e[0] - m), p1 = __expf(e[1] - m);
    float s = p0 + p1;
#pragma unroll
    for (int o = 16; o > 0; o >>= 1) s += __shfl_xor_sync(0xffffffffu, s, o);
    float inv = 1.f / s;

#pragma unroll
    for (int tgt = 0; tgt < 2; tgt++) {
        int a = aidx[tgt];
        float r0 = sh_raw[h * 16 + 0 + a], r1 = sh_raw[h * 16 + 4 + a];
        float r2 = sh_raw[h * 16 + 8 + a], r3 = sh_raw[h * 16 + 12 + a];
        float m4 = fmaxf(fmaxf(r0, r1), fmaxf(r2, r3));
        float s4 = __expf(r0 - m4) + __expf(r1 - m4) + __expf(r2 - m4) + __expf(r3 - m4);
        float lw = __expf(e[tgt] - m4) / s4;
        float sw = (tgt == 0 ? p0 : p1) * inv;
        sh_swlw[h][lane + 32 * tgt] = make_float2(sw, lw);
    }

    // ---- phase 1: per-sample indices (half2 units, +head offset) + weights
    const float rcx = refwin[bq * 4 + 0];
    const float rcy = refwin[bq * 4 + 1];
    const float rsx = refwin[bq * 4 + 2];
    const float rsy = refwin[bq * 4 + 3];

#pragma unroll
    for (int rep = 0; rep < 2; rep++) {
        int sidx = t + rep * 256;
        int hh = sidx >> 6;
        int n  = sidx & 63;
        int l  = n >> 4;
        int ii = (n >> 2) & 3;
        int jj = n & 3;

        float o0 = sh_off[hh * 16 + l * 4 + 0];
        float o1 = sh_off[hh * 16 + l * 4 + 1];
        float o2 = sh_off[hh * 16 + l * 4 + 2];
        float o3 = sh_off[hh * 16 + l * 4 + 3];
        float cx = rcx + o0 * 0.125f * rsx;
        float cy = rcy + o1 * 0.125f * rsy;
        float sx = fmaxf(rsx + o2 * 0.125f * rsx, 0.f);
        float sy = fmaxf(rsy + o3 * 0.125f * rsy, 0.f);

        int   Wl  = 128 >> l;
        float fW  = (float)Wl;
        int base  = (l == 0) ? 0 : (l == 1) ? 16384 : (l == 2) ? 20480 : 21504;

        float y   = (cy + ((float)ii - 1.5f) * 0.25f * sy) * fW - 0.5f;
        float x   = (cx + ((float)jj - 1.5f) * 0.25f * sx) * fW - 0.5f;
        float y0f = floorf(y);
        float x0f = floorf(x);
        float fy  = y - y0f;
        float fx  = x - x0f;
        int y0 = (int)y0f;
        int x0 = (int)x0f;
        bool vy0 = (y0 >= 0) && (y0 < Wl);
        bool vy1 = (y0 >= -1) && (y0 < Wl - 1);
        bool vx0 = (x0 >= 0) && (x0 < Wl);
        bool vx1 = (x0 >= -1) && (x0 < Wl - 1);
        int cy0 = min(max(y0, 0), Wl - 1);
        int cy1 = min(max(y0 + 1, 0), Wl - 1);
        int cx0 = min(max(x0, 0), Wl - 1);
        int cx1 = min(max(x0 + 1, 0), Wl - 1);

        int hofs = hh * 16;           // head offset in half2 units
        int4 id;
        id.x = (base + cy0 * Wl + cx0) * 128 + hofs;
        id.y = (base + cy0 * Wl + cx1) * 128 + hofs;
        id.z = (base + cy1 * Wl + cx0) * 128 + hofs;
        id.w = (base + cy1 * Wl + cx1) * 128 + hofs;
        float4 w;
        w.x = (vx0 && vy0) ? (1.f - fx) * (1.f - fy) : 0.f;
        w.y = (vx1 && vy0) ? fx * (1.f - fy) : 0.f;
        w.z = (vx0 && vy1) ? (1.f - fx) * fy : 0.f;
        w.w = (vx1 && vy1) ? fx * fy : 0.f;
        sh_idx[sidx] = id;
        sh_w[sidx]   = w;
    }
    __syncthreads();

    // ---- phase 2: half2 gather, 2 samples per iteration ----
    const int sp = lane >> 4;       // sample parity
    const int lo = lane & 15;       // half2 channel pair within head
    const __half2* vb2 = (const __half2*)g_v16 + (size_t)b * (L2_ * 128);

    float2 ao = make_float2(0.f, 0.f);
    float2 am = make_float2(0.f, 0.f);

#pragma unroll 8
    for (int n = 0; n < 64; n += 2) {
        int4   id = sh_idx[h * 64 + n + sp];
        float4 w  = sh_w[h * 64 + n + sp];
        float2 v0 = __half22float2(vb2[id.x + lo]);
        float2 v1 = __half22float2(vb2[id.y + lo]);
        float2 v2 = __half22float2(vb2[id.z + lo]);
        float2 v3 = __half22float2(vb2[id.w + lo]);
        float vx = w.x * v0.x + w.y * v1.x + w.z * v2.x + w.w * v3.x;
        float vy = w.x * v0.y + w.y * v1.y + w.z * v2.y + w.w * v3.y;
        float2 sl = sh_swlw[h][n + sp];
        ao.x += sl.x * vx;  ao.y += sl.x * vy;
        am.x += sl.y * vx;  am.y += sl.y * vy;
    }

    // reduce across the two sample-parity halves (lanes lo and lo+16)
    ao.x += __shfl_xor_sync(0xffffffffu, ao.x, 16);
    ao.y += __shfl_xor_sync(0xffffffffu, ao.y, 16);
    am.x += __shfl_xor_sync(0xffffffffu, am.x, 16);
    am.y += __shfl_xor_sync(0xffffffffu, am.y, 16);

    if (sp == 0) {
        size_t od = (size_t)bq * D_ + h * HD_ + lo * 2;
        *(float2*)(g_outpre  + od) = ao;
        *(float2*)(g_moutpre + od) = am;
    }
}

// ---------------------------------------------------------------------------
extern "C" void kernel_launch(void* const* d_in, const int* in_sizes, int n_in,
                              void* d_out, int out_size)
{
    const float* query = (const float*)d_in[0];
    const float* value = (const float*)d_in[1];
    const float* refw  = (const float*)d_in[2];
    const float* Wv    = (const float*)d_in[3];
    const float* bv    = (const float*)d_in[4];
    const float* Wo    = (const float*)d_in[5];
    const float* bo    = (const float*)d_in[6];
    const float* Wbox  = (const float*)d_in[7];
    const float* bbox  = (const float*)d_in[8];
    const float* Wattn = (const float*)d_in[9];
    const float* battn = (const float*)d_in[10];
    const unsigned char* vmask = (const unsigned char*)d_in[13];

    float* out   = (float*)d_out;
    float* mout  = out  + (size_t)NQ_ * D_;
    float* awout = mout + (size_t)NQ_ * D_;

    float *pqp, *pop, *pmp, *pbq;
    __half *pv16, *pwvh, *pwoh, *pwol, *pwqh, *pwql;
    cudaGetSymbolAddress((void**)&pv16,   g_v16);
    cudaGetSymbolAddress((void**)&pqp,    g_qproj);
    cudaGetSymbolAddress((void**)&pop,    g_outpre);
    cudaGetSymbolAddress((void**)&pmp,    g_moutpre);
    cudaGetSymbolAddress((void**)&pwvh,   g_Wvh);
    cudaGetSymbolAddress((void**)&pwoh,   g_Woh);
    cudaGetSymbolAddress((void**)&pwol,   g_Wol);
    cudaGetSymbolAddress((void**)&pwqh,   g_Wqh);
    cudaGetSymbolAddress((void**)&pwql,   g_Wql);
    cudaGetSymbolAddress((void**)&pbq,    g_bq);

    const int VSMEM = VW_SZ + 2 * VA_BUF + 1024;   // 148480
    cudaFuncSetAttribute(hmma_gemm_v,
                         cudaFuncAttributeMaxDynamicSharedMemorySize, VSMEM);

    // 0) prep: weights -> fp16
    prep_w_kernel<<<256, 256>>>(Wv, Wo, Wbox, Wattn, bbox, battn);
    // 1) fused q projection
    hmma_gemm_fp16<<<dim3(NQ_ / 128, 1), 512>>>(query, query, pwqh, pwql, pbq,
                                                pqp, pqp);
    // 2) v = value @ Wv^T + bv (fp16 out, masked; W-resident, fused convert)
    hmma_gemm_v<<<MV_ / 128, 512, VSMEM>>>(value, pwvh, bv, pv16, vmask);
    // 3) softmaxes + sampling
    sample_kernel<<<NQ_, 256>>>(refw, awout);
    // 4) out + mout projections (fused, one launch)
    hmma_gemm_fp16<<<dim3(NQ_ / 128, 2), 512>>>(pop, pmp, pwoh, pwol, bo,
                                                out, mout);
}

// round 15
// speedup vs baseline: 2.0854x; 1.0755x over previous
#include <cuda_runtime.h>
#include <cuda_fp16.h>
#include <cstdint>
#include <cstring>

#define B_   4
#define L1_  1024
#define D_   256
#define H_   8
#define HD_  32
#define L_   4
#define L2_  21760
#define NQ_  (B_ * L1_)          // 4096
#define MV_  (B_ * L2_)          // 87040

// ---------------- scratch (static device memory; no allocs) ----------------
__device__ __half g_v16[(size_t)MV_ * D_];      // fp16 v = value @ Wv^T (44.5 MB)
__device__ float  g_qproj[(size_t)NQ_ * 256];   // [off | aw] fused projection
__device__ float  g_outpre[(size_t)NQ_ * D_];
__device__ float  g_moutpre[(size_t)NQ_ * D_];
__device__ __half g_Wvh[65536];                 // Wv fp16 (single pass)
__device__ __half g_Woh[65536], g_Wol[65536];   // Wo fp16 hi/lo
__device__ __half g_Wqh[65536], g_Wql[65536];   // [Wbox;Wattn] fp16 hi/lo
__device__ float  g_bq[256];                    // [bbox | battn]

// ===========================================================================
// helpers
// ===========================================================================
__device__ __forceinline__ uint32_t h2_bits(__half2 h) {
    uint32_t u;
    memcpy(&u, &h, 4);
    return u;
}
__device__ __forceinline__ __half2 bits_h2(uint32_t u) {
    __half2 h;
    memcpy(&h, &u, 4);
    return h;
}
__device__ __forceinline__ uint32_t smem_u32(const void* p) {
    uint32_t a;
    asm("{ .reg .u64 t; cvta.to.shared.u64 t, %1; cvt.u32.u64 %0, t; }"
        : "=r"(a) : "l"(p));
    return a;
}
__device__ __forceinline__ void ldmx4(uint32_t addr, uint32_t& r0, uint32_t& r1,
                                      uint32_t& r2, uint32_t& r3) {
    asm volatile("ldmatrix.sync.aligned.m8n8.x4.shared.b16 {%0,%1,%2,%3}, [%4];"
                 : "=r"(r0), "=r"(r1), "=r"(r2), "=r"(r3) : "r"(addr));
}
__device__ __forceinline__ void mma16816(float* d, const uint32_t* a,
                                         const uint32_t* b) {
    asm volatile("mma.sync.aligned.m16n8k16.row.col.f32.f16.f16.f32 "
                 "{%0,%1,%2,%3}, {%4,%5,%6,%7}, {%8,%9}, {%0,%1,%2,%3};"
                 : "+f"(d[0]), "+f"(d[1]), "+f"(d[2]), "+f"(d[3])
                 : "r"(a[0]), "r"(a[1]), "r"(a[2]), "r"(a[3]),
                   "r"(b[0]), "r"(b[1]));
}
#define CP_ASYNC16(dst, src) \
    asm volatile("cp.async.cg.shared.global [%0], [%1], 16;" :: "r"(dst), "l"(src))
#define CP_COMMIT() asm volatile("cp.async.commit_group;" ::: "memory")
#define CP_WAIT0()  asm volatile("cp.async.wait_group 0;" ::: "memory")

// ---------------------------------------------------------------------------
// prep: weights -> fp16 (Wv single, Wo/[Wbox;Wattn] hi/lo); bias pack
// ---------------------------------------------------------------------------
__global__ void prep_w_kernel(const float* __restrict__ Wv,
                              const float* __restrict__ Wo,
                              const float* __restrict__ Wbox,
                              const float* __restrict__ Wattn,
                              const float* __restrict__ bbox,
                              const float* __restrict__ battn)
{
    int i = blockIdx.x * blockDim.x + threadIdx.x;   // 0..65535
    g_Wvh[i] = __float2half_rn(Wv[i]);
    float o = Wo[i];
    __half ho = __float2half_rn(o);
    g_Woh[i] = ho;
    g_Wol[i] = __float2half_rn(o - __half2float(ho));
    int r = i >> 8, c = i & 255;
    float q = (r < 128) ? Wbox[r * 256 + c] : Wattn[(r - 128) * 256 + c];
    __half hq = __float2half_rn(q);
    g_Wqh[i] = hq;
    g_Wql[i] = __float2half_rn(q - __half2float(hq));
    if (i < 256) g_bq[i] = (i < 128) ? bbox[i] : battn[i - 128];
}

// ===========================================================================
// Value GEMM (persistent CTAs): 136 CTAs x 5 tiles; W loaded to smem ONCE per
// CTA; A fp32 -> fp16 fused staging with 2x8KB double buffer per tile.
// ===========================================================================
#define VW_SZ     131072
#define VA_BUF    8192
#define V_CTAS    136
#define V_TILES   (MV_ / 128)     // 680
__global__ __launch_bounds__(512)
void hmma_gemm_v(const float* __restrict__ A,
                 const __half* __restrict__ Wh,
                 const float* __restrict__ bias,
                 __half* __restrict__ C,
                 const unsigned char* __restrict__ mask)
{
    extern __shared__ __align__(16) unsigned char dsm[];
    float* bias_s = (float*)(dsm + VW_SZ + 2 * VA_BUF);

    const int t    = threadIdx.x;
    const int wid  = t >> 5;
    const int lane = t & 31;
    const int wm   = wid & 3;
    const int wn   = wid >> 2;
    const uint32_t base  = smem_u32(dsm);
    const uint32_t abase = base + VW_SZ;

    if (t < 256) bias_s[t] = bias[t];

    // ---- W prologue: once per CTA ----
#pragma unroll
    for (int u = 0; u < 16; u++) {
        int f  = t + u * 512;
        int r  = f >> 5;
        int j  = f & 31;
        int ch = j >> 2;
        int cu = j & 3;
        uint32_t dst = base + ch * 16384 + r * 64 + ((cu ^ ((r >> 1) & 3)) * 16);
        CP_ASYNC16(dst, Wh + (size_t)r * 256 + j * 8);
    }
    CP_COMMIT();
    CP_WAIT0();
    __syncthreads();

    const int ar = t >> 2;
    const int au = t & 3;
    const uint32_t asw = ((au ^ ((ar >> 1) & 3)) * 16) + ar * 64;

    for (int tile = blockIdx.x; tile < V_TILES; tile += V_CTAS) {
        const int m0 = tile * 128;
        const float* asrc = A + (size_t)(m0 + ar) * 256 + au * 8;

        float acc[2][8][4];
#pragma unroll
        for (int mt = 0; mt < 2; mt++)
#pragma unroll
            for (int nt = 0; nt < 8; nt++)
#pragma unroll
                for (int i = 0; i < 4; i++) acc[mt][nt][i] = 0.f;

        float4 pa0 = *(const float4*)(asrc);
        float4 pa1 = *(const float4*)(asrc + 4);
        {
            uint4 u;
            u.x = h2_bits(__floats2half2_rn(pa0.x, pa0.y));
            u.y = h2_bits(__floats2half2_rn(pa0.z, pa0.w));
            u.z = h2_bits(__floats2half2_rn(pa1.x, pa1.y));
            u.w = h2_bits(__floats2half2_rn(pa1.z, pa1.w));
            *(uint4*)(dsm + VW_SZ + asw) = u;
        }
        __syncthreads();

        for (int ch = 0; ch < 8; ch++) {
            if (ch < 7) {
                pa0 = *(const float4*)(asrc + (ch + 1) * 32);
                pa1 = *(const float4*)(asrc + (ch + 1) * 32 + 4);
            }

            const uint32_t uA = abase + (ch & 1) * VA_BUF;
            const uint32_t uB = base + ch * 16384;

#pragma unroll
            for (int s = 0; s < 2; s++) {
                uint32_t ah[2][4];
#pragma unroll
                for (int mt = 0; mt < 2; mt++) {
                    int row  = wm * 32 + mt * 16 + (lane & 15);
                    int unit = s * 2 + (lane >> 4);
                    ldmx4(uA + row * 64 + (unit ^ ((row >> 1) & 3)) * 16,
                          ah[mt][0], ah[mt][1], ah[mt][2], ah[mt][3]);
                }
#pragma unroll
                for (int half = 0; half < 2; half++) {
                    uint32_t bh[4][2];
#pragma unroll
                    for (int p = 0; p < 2; p++) {
                        int pp   = half * 2 + p;
                        int nrow = wn * 64 + pp * 16 + (lane & 7) + (((lane >> 4) & 1) << 3);
                        int unit = s * 2 + ((lane >> 3) & 1);
                        uint32_t off = nrow * 64 + (unit ^ ((nrow >> 1) & 3)) * 16;
                        ldmx4(uB + off, bh[p*2][0], bh[p*2][1], bh[p*2+1][0], bh[p*2+1][1]);
                    }
#pragma unroll
                    for (int mt = 0; mt < 2; mt++)
#pragma unroll
                        for (int q = 0; q < 4; q++)
                            mma16816(acc[mt][half * 4 + q], ah[mt], bh[q]);
                }
            }

            if (ch < 7) {
                uint4 u;
                u.x = h2_bits(__floats2half2_rn(pa0.x, pa0.y));
                u.y = h2_bits(__floats2half2_rn(pa0.z, pa0.w));
                u.z = h2_bits(__floats2half2_rn(pa1.x, pa1.y));
                u.w = h2_bits(__floats2half2_rn(pa1.z, pa1.w));
                *(uint4*)(dsm + VW_SZ + ((ch + 1) & 1) * VA_BUF + asw) = u;
                __syncthreads();
            }
        }

        // epilogue: bias + mask, fp16 stores
        const int rw = lane >> 2;
        const int cw = (lane & 3) * 2;
#pragma unroll
        for (int mt = 0; mt < 2; mt++) {
            int r = m0 + wm * 32 + mt * 16 + rw;
            bool z0 = mask[r] != 0;
            bool z1 = mask[r + 8] != 0;
#pragma unroll
            for (int nt = 0; nt < 8; nt++) {
                int cl = wn * 64 + nt * 8 + cw;
                float b0 = bias_s[cl], b1 = bias_s[cl + 1];
                __half2 v0 = __floats2half2_rn(z0 ? 0.f : acc[mt][nt][0] + b0,
                                               z0 ? 0.f : acc[mt][nt][1] + b1);
                __half2 v1 = __floats2half2_rn(z1 ? 0.f : acc[mt][nt][2] + b0,
                                               z1 ? 0.f : acc[mt][nt][3] + b1);
                *(__half2*)(C + (size_t)r * 256 + cl)       = v0;
                *(__half2*)(C + (size_t)(r + 8) * 256 + cl) = v1;
            }
        }
        __syncthreads();   // protect A buffers before next tile overwrites
    }
}

// ===========================================================================
// fp32-A 2-pass HMMA GEMM (q-projection, out/mout): C[M,256] fp32.
// ===========================================================================
__global__ __launch_bounds__(512)
void hmma_gemm_fp16(const float* __restrict__ A0,
                    const float* __restrict__ A1,
                    const __half* __restrict__ Wh,
                    const __half* __restrict__ Wl,
                    const float* __restrict__ bias,
                    float* __restrict__ C0,
                    float* __restrict__ C1)
{
    __shared__ __align__(16) unsigned char smA [128 * 64];
    __shared__ __align__(16) unsigned char smBh[256 * 64];
    __shared__ __align__(16) unsigned char smBl[256 * 64];
    __shared__ float bias_s[256];

    const float* A = blockIdx.y ? A1 : A0;
    float*       C = blockIdx.y ? C1 : C0;

    const int t    = threadIdx.x;
    const int wid  = t >> 5;
    const int lane = t & 31;
    const int wm   = wid & 3;
    const int wn   = wid >> 2;
    const int m0   = blockIdx.x * 128;

    if (t < 256) bias_s[t] = bias[t];

    float acc[2][8][4];
#pragma unroll
    for (int mt = 0; mt < 2; mt++)
#pragma unroll
        for (int nt = 0; nt < 8; nt++)
#pragma unroll
            for (int i = 0; i < 4; i++) acc[mt][nt][i] = 0.f;

    const uint32_t uA  = smem_u32(smA);
    const uint32_t uBh = smem_u32(smBh);
    const uint32_t uBl = smem_u32(smBl);

    for (int k0 = 0; k0 < 256; k0 += 32) {
        {
            int r  = t >> 2;
            int c4 = t & 3;
            const float* src = A + (size_t)(m0 + r) * 256 + k0 + c4 * 8;
            float4 v0 = *(const float4*)(src);
            float4 v1 = *(const float4*)(src + 4);
            uint4 u;
            u.x = h2_bits(__floats2half2_rn(v0.x, v0.y));
            u.y = h2_bits(__floats2half2_rn(v0.z, v0.w));
            u.z = h2_bits(__floats2half2_rn(v1.x, v1.y));
            u.w = h2_bits(__floats2half2_rn(v1.z, v1.w));
            *(uint4*)(smA + r * 64 + (c4 ^ ((r >> 1) & 3)) * 16) = u;
        }
#pragma unroll
        for (int u = 0; u < 2; u++) {
            int f   = t + u * 512;
            int r   = f >> 2;
            int c16 = f & 3;
            uint32_t dst = r * 64 + (c16 ^ ((r >> 1) & 3)) * 16;
            *(uint4*)(smBh + dst) = *(const uint4*)(Wh + (size_t)r * 256 + k0 + c16 * 8);
            *(uint4*)(smBl + dst) = *(const uint4*)(Wl + (size_t)r * 256 + k0 + c16 * 8);
        }
        __syncthreads();

#pragma unroll
        for (int s = 0; s < 2; s++) {
            uint32_t ah[2][4];
#pragma unroll
            for (int mt = 0; mt < 2; mt++) {
                int row  = wm * 32 + mt * 16 + (lane & 15);
                int unit = s * 2 + (lane >> 4);
                ldmx4(uA + row * 64 + (unit ^ ((row >> 1) & 3)) * 16,
                      ah[mt][0], ah[mt][1], ah[mt][2], ah[mt][3]);
            }
#pragma unroll
            for (int half = 0; half < 2; half++) {
                uint32_t bh[4][2], bl[4][2];
#pragma unroll
                for (int p = 0; p < 2; p++) {
                    int pp   = half * 2 + p;
                    int nrow = wn * 64 + pp * 16 + (lane & 7) + (((lane >> 4) & 1) << 3);
                    int unit = s * 2 + ((lane >> 3) & 1);
                    uint32_t off = nrow * 64 + (unit ^ ((nrow >> 1) & 3)) * 16;
                    ldmx4(uBh + off, bh[p*2][0], bh[p*2][1], bh[p*2+1][0], bh[p*2+1][1]);
                    ldmx4(uBl + off, bl[p*2][0], bl[p*2][1], bl[p*2+1][0], bl[p*2+1][1]);
                }
#pragma unroll
                for (int mt = 0; mt < 2; mt++)
#pragma unroll
                    for (int q = 0; q < 4; q++) {
                        int nt = half * 4 + q;
                        mma16816(acc[mt][nt], ah[mt], bh[q]);
                        mma16816(acc[mt][nt], ah[mt], bl[q]);
                    }
            }
        }
        __syncthreads();
    }

    const int rw = lane >> 2;
    const int cw = (lane & 3) * 2;
#pragma unroll
    for (int mt = 0; mt < 2; mt++) {
        int r = m0 + wm * 32 + mt * 16 + rw;
#pragma unroll
        for (int nt = 0; nt < 8; nt++) {
            int cl = wn * 64 + nt * 8 + cw;
            float b0 = bias_s[cl], b1 = bias_s[cl + 1];
            float2 v0 = make_float2(acc[mt][nt][0] + b0, acc[mt][nt][1] + b1);
            float2 v1 = make_float2(acc[mt][nt][2] + b0, acc[mt][nt][3] + b1);
            *(float2*)(C + (size_t)r * 256 + cl)       = v0;
            *(float2*)(C + (size_t)(r + 8) * 256 + cl) = v1;
        }
    }
}

// ---------------------------------------------------------------------------
// Sampler v4: 4 samples/iteration, LDG.64 gather lanes.
// lane = (sp2 = lane>>3) sample subgroup 0..3, (lo = lane&7) 4-channel slot.
// ---------------------------------------------------------------------------
__global__ __launch_bounds__(256)
void sample_kernel(const float* __restrict__ refwin,
                   float* __restrict__ awout)
{
    __shared__ float  sh_raw[128];
    __shared__ float  sh_off[128];
    __shared__ float2 sh_swlw[H_][64];
    __shared__ int4   sh_idx[512];
    __shared__ float4 sh_w[512];

    const int bq   = blockIdx.x;
    const int b    = bq >> 10;
    const int t    = threadIdx.x;
    const int h    = t >> 5;
    const int lane = t & 31;

    if (t < 128) sh_off[t] = g_qproj[(size_t)bq * 256 + t];
    else         sh_raw[t - 128] = g_qproj[(size_t)bq * 256 + t];
    __syncthreads();

    // ---- softmaxes (warp = head) ----
    float e[2];
    int   aidx[2];
#pragma unroll
    for (int tgt = 0; tgt < 2; tgt++) {
        int n = lane + 32 * tgt;
        int l = n >> 4, kk = n & 15, ii = kk >> 2, jj = kk & 3;
        int a = ((ii >> 1) << 1) + (jj >> 1);
        aidx[tgt] = a;
        e[tgt] = sh_raw[h * 16 + l * 4 + a];
    }
    awout[(size_t)bq * 512 + h * 64 + lane]      = e[0];
    awout[(size_t)bq * 512 + h * 64 + lane + 32] = e[1];

    float m = fmaxf(e[0], e[1]);
#pragma unroll
    for (int o = 16; o > 0; o >>= 1) m = fmaxf(m, __shfl_xor_sync(0xffffffffu, m, o));
    float p0 = __expf(e[0] - m), p1 = __expf(e[1] - m);
    float s = p0 + p1;
#pragma unroll
    for (int o = 16; o > 0; o >>= 1) s += __shfl_xor_sync(0xffffffffu, s, o);
    float inv = 1.f / s;

#pragma unroll
    for (int tgt = 0; tgt < 2; tgt++) {
        int a = aidx[tgt];
        float r0 = sh_raw[h * 16 + 0 + a], r1 = sh_raw[h * 16 + 4 + a];
        float r2 = sh_raw[h * 16 + 8 + a], r3 = sh_raw[h * 16 + 12 + a];
        float m4 = fmaxf(fmaxf(r0, r1), fmaxf(r2, r3));
        float s4 = __expf(r0 - m4) + __expf(r1 - m4) + __expf(r2 - m4) + __expf(r3 - m4);
        float lw = __expf(e[tgt] - m4) / s4;
        float sw = (tgt == 0 ? p0 : p1) * inv;
        sh_swlw[h][lane + 32 * tgt] = make_float2(sw, lw);
    }

    // ---- phase 1: per-sample indices (half2 units, +head offset) + weights
    const float rcx = refwin[bq * 4 + 0];
    const float rcy = refwin[bq * 4 + 1];
    const float rsx = refwin[bq * 4 + 2];
    const float rsy = refwin[bq * 4 + 3];

#pragma unroll
    for (int rep = 0; rep < 2; rep++) {
        int sidx = t + rep * 256;
        int hh = sidx >> 6;
        int n  = sidx & 63;
        int l  = n >> 4;
        int ii = (n >> 2) & 3;
        int jj = n & 3;

        float o0 = sh_off[hh * 16 + l * 4 + 0];
        float o1 = sh_off[hh * 16 + l * 4 + 1];
        float o2 = sh_off[hh * 16 + l * 4 + 2];
        float o3 = sh_off[hh * 16 + l * 4 + 3];
        float cx = rcx + o0 * 0.125f * rsx;
        float cy = rcy + o1 * 0.125f * rsy;
        float sx = fmaxf(rsx + o2 * 0.125f * rsx, 0.f);
        float sy = fmaxf(rsy + o3 * 0.125f * rsy, 0.f);

        int   Wl  = 128 >> l;
        float fW  = (float)Wl;
        int base  = (l == 0) ? 0 : (l == 1) ? 16384 : (l == 2) ? 20480 : 21504;

        float y   = (cy + ((float)ii - 1.5f) * 0.25f * sy) * fW - 0.5f;
        float x   = (cx + ((float)jj - 1.5f) * 0.25f * sx) * fW - 0.5f;
        float y0f = floorf(y);
        float x0f = floorf(x);
        float fy  = y - y0f;
        float fx  = x - x0f;
        int y0 = (int)y0f;
        int x0 = (int)x0f;
        bool vy0 = (y0 >= 0) && (y0 < Wl);
        bool vy1 = (y0 >= -1) && (y0 < Wl - 1);
        bool vx0 = (x0 >= 0) && (x0 < Wl);
        bool vx1 = (x0 >= -1) && (x0 < Wl - 1);
        int cy0 = min(max(y0, 0), Wl - 1);
        int cy1 = min(max(y0 + 1, 0), Wl - 1);
        int cx0 = min(max(x0, 0), Wl - 1);
        int cx1 = min(max(x0 + 1, 0), Wl - 1);

        int hofs = hh * 16;           // head offset in half2 units
        int4 id;
        id.x = (base + cy0 * Wl + cx0) * 128 + hofs;
        id.y = (base + cy0 * Wl + cx1) * 128 + hofs;
        id.z = (base + cy1 * Wl + cx0) * 128 + hofs;
        id.w = (base + cy1 * Wl + cx1) * 128 + hofs;
        float4 w;
        w.x = (vx0 && vy0) ? (1.f - fx) * (1.f - fy) : 0.f;
        w.y = (vx1 && vy0) ? fx * (1.f - fy) : 0.f;
        w.z = (vx0 && vy1) ? (1.f - fx) * fy : 0.f;
        w.w = (vx1 && vy1) ? fx * fy : 0.f;
        sh_idx[sidx] = id;
        sh_w[sidx]   = w;
    }
    __syncthreads();

    // ---- phase 2: 4 samples per iteration, 8B loads (4 channels/lane) ----
    const int sp2 = lane >> 3;      // sample subgroup 0..3
    const int lo  = lane & 7;       // 4-channel slot (2 half2)
    const __half2* vb2 = (const __half2*)g_v16 + (size_t)b * (L2_ * 128);

    float4 ao = make_float4(0.f, 0.f, 0.f, 0.f);
    float4 am = make_float4(0.f, 0.f, 0.f, 0.f);

#pragma unroll 4
    for (int n = 0; n < 64; n += 4) {
        int4   id = sh_idx[h * 64 + n + sp2];
        float4 w  = sh_w[h * 64 + n + sp2];

        uint2 u0 = *(const uint2*)(vb2 + id.x + lo * 2);
        uint2 u1 = *(const uint2*)(vb2 + id.y + lo * 2);
        uint2 u2 = *(const uint2*)(vb2 + id.z + lo * 2);
        uint2 u3 = *(const uint2*)(vb2 + id.w + lo * 2);

        float2 a0 = __half22float2(bits_h2(u0.x));
        float2 b0 = __half22float2(bits_h2(u0.y));
        float2 a1 = __half22float2(bits_h2(u1.x));
        float2 b1 = __half22float2(bits_h2(u1.y));
        float2 a2 = __half22float2(bits_h2(u2.x));
        float2 b2 = __half22float2(bits_h2(u2.y));
        float2 a3 = __half22float2(bits_h2(u3.x));
        float2 b3 = __half22float2(bits_h2(u3.y));

        float c0 = w.x * a0.x + w.y * a1.x + w.z * a2.x + w.w * a3.x;
        float c1 = w.x * a0.y + w.y * a1.y + w.z * a2.y + w.w * a3.y;
        float c2 = w.x * b0.x + w.y * b1.x + w.z * b2.x + w.w * b3.x;
        float c3 = w.x * b0.y + w.y * b1.y + w.z * b2.y + w.w * b3.y;

        float2 sl = sh_swlw[h][n + sp2];
        ao.x += sl.x * c0;  ao.y += sl.x * c1;
        ao.z += sl.x * c2;  ao.w += sl.x * c3;
        am.x += sl.y * c0;  am.y += sl.y * c1;
        am.z += sl.y * c2;  am.w += sl.y * c3;
    }

    // reduce across the 4 sample subgroups (xor 8, then xor 16)
#pragma unroll
    for (int o = 8; o <= 16; o <<= 1) {
        ao.x += __shfl_xor_sync(0xffffffffu, ao.x, o);
        ao.y += __shfl_xor_sync(0xffffffffu, ao.y, o);
        ao.z += __shfl_xor_sync(0xffffffffu, ao.z, o);
        ao.w += __shfl_xor_sync(0xffffffffu, ao.w, o);
        am.x += __shfl_xor_sync(0xffffffffu, am.x, o);
        am.y += __shfl_xor_sync(0xffffffffu, am.y, o);
        am.z += __shfl_xor_sync(0xffffffffu, am.z, o);
        am.w += __shfl_xor_sync(0xffffffffu, am.w, o);
    }

    if (sp2 == 0) {
        size_t od = (size_t)bq * D_ + h * HD_ + lo * 4;
        *(float4*)(g_outpre  + od) = ao;
        *(float4*)(g_moutpre + od) = am;
    }
}

// ---------------------------------------------------------------------------
extern "C" void kernel_launch(void* const* d_in, const int* in_sizes, int n_in,
                              void* d_out, int out_size)
{
    const float* query = (const float*)d_in[0];
    const float* value = (const float*)d_in[1];
    const float* refw  = (const float*)d_in[2];
    const float* Wv    = (const float*)d_in[3];
    const float* bv    = (const float*)d_in[4];
    const float* Wo    = (const float*)d_in[5];
    const float* bo    = (const float*)d_in[6];
    const float* Wbox  = (const float*)d_in[7];
    const float* bbox  = (const float*)d_in[8];
    const float* Wattn = (const float*)d_in[9];
    const float* battn = (const float*)d_in[10];
    const unsigned char* vmask = (const unsigned char*)d_in[13];

    float* out   = (float*)d_out;
    float* mout  = out  + (size_t)NQ_ * D_;
    float* awout = mout + (size_t)NQ_ * D_;

    float *pqp, *pop, *pmp, *pbq;
    __half *pv16, *pwvh, *pwoh, *pwol, *pwqh, *pwql;
    cudaGetSymbolAddress((void**)&pv16,   g_v16);
    cudaGetSymbolAddress((void**)&pqp,    g_qproj);
    cudaGetSymbolAddress((void**)&pop,    g_outpre);
    cudaGetSymbolAddress((void**)&pmp,    g_moutpre);
    cudaGetSymbolAddress((void**)&pwvh,   g_Wvh);
    cudaGetSymbolAddress((void**)&pwoh,   g_Woh);
    cudaGetSymbolAddress((void**)&pwol,   g_Wol);
    cudaGetSymbolAddress((void**)&pwqh,   g_Wqh);
    cudaGetSymbolAddress((void**)&pwql,   g_Wql);
    cudaGetSymbolAddress((void**)&pbq,    g_bq);

    const int VSMEM = VW_SZ + 2 * VA_BUF + 1024;   // 148480
    cudaFuncSetAttribute(hmma_gemm_v,
                         cudaFuncAttributeMaxDynamicSharedMemorySize, VSMEM);

    // 0) prep: weights -> fp16
    prep_w_kernel<<<256, 256>>>(Wv, Wo, Wbox, Wattn, bbox, battn);
    // 1) fused q projection
    hmma_gemm_fp16<<<dim3(NQ_ / 128, 1), 512>>>(query, query, pwqh, pwql, pbq,
                                                pqp, pqp);
    // 2) v = value @ Wv^T + bv (persistent CTAs, W loaded once per CTA)
    hmma_gemm_v<<<V_CTAS, 512, VSMEM>>>(value, pwvh, bv, pv16, vmask);
    // 3) softmaxes + sampling
    sample_kernel<<<NQ_, 256>>>(refw, awout);
    // 4) out + mout projections (fused, one launch)
    hmma_gemm_fp16<<<dim3(NQ_ / 128, 2), 512>>>(pop, pmp, pwoh, pwol, bo,
                                                out, mout);
}